// round 14
// baseline (speedup 1.0000x reference)
#include <cuda_runtime.h>
#include <cuda_bf16.h>
#include <math.h>
#include <stdint.h>

#define NN 50000
#define EE 800000
#define HD 128

// ---------------- scratch (device globals: no allocation allowed) -----------
// g_deg and g_esum are SELF-RESTORING: zero at module load, consumed-and-
// re-zeroed inside scan1 / spmm64 respectively, so every kernel_launch call
// (correctness run and each graph replay) starts from the same state.
__device__ __align__(16) float g_h [NN * HD];     // fp32 gemm out / gather src
__device__ __align__(16) float g_t2[NN * HD];     // fp32 gemm out / gather src
__device__ __align__(16) __nv_bfloat16 g_sh[NN * HD];  // split-hi gemm input
__device__ __align__(16) __nv_bfloat16 g_sl[NN * HD];  // split-lo gemm input
__device__ __align__(16) __nv_bfloat16 g_whT[3 * 128 * 128 + 64 * 128];
__device__ __align__(16) __nv_bfloat16 g_wlT[3 * 128 * 128 + 64 * 128];
__device__ float    g_el[NN];
__device__ float    g_er[NN];
__device__ float    g_esum[NN];
__device__ int      g_rank[EE];       // edge rank within its dst row
__device__ int      g_deg[NN];
__device__ int      g_rowptr[NN + 1];
__device__ int      g_bsum[256];
__device__ int      g_csrs[EE];
__device__ float    g_csra[EE];       // exp(e) in CSR order (unnormalized)
__device__ int      g_is64;

// ---------------- helpers -----------------------------------------------------
__device__ __forceinline__ void split2(float a, float b, uint32_t& hi, uint32_t& lo) {
    __nv_bfloat16 h0 = __float2bfloat16(a);
    __nv_bfloat16 h1 = __float2bfloat16(b);
    __nv_bfloat16 l0 = __float2bfloat16(a - __bfloat162float(h0));
    __nv_bfloat16 l1 = __float2bfloat16(b - __bfloat162float(h1));
    hi = (uint32_t)__bfloat16_as_ushort(h0) | ((uint32_t)__bfloat16_as_ushort(h1) << 16);
    lo = (uint32_t)__bfloat16_as_ushort(l0) | ((uint32_t)__bfloat16_as_ushort(l1) << 16);
}

__device__ __forceinline__ void mma16816(float* c,
        uint32_t a0, uint32_t a1, uint32_t a2, uint32_t a3,
        uint32_t b0, uint32_t b1) {
    asm volatile(
        "mma.sync.aligned.m16n8k16.row.col.f32.bf16.bf16.f32 "
        "{%0,%1,%2,%3}, {%4,%5,%6,%7}, {%8,%9}, {%0,%1,%2,%3};"
        : "+f"(c[0]), "+f"(c[1]), "+f"(c[2]), "+f"(c[3])
        : "r"(a0), "r"(a1), "r"(a2), "r"(a3), "r"(b0), "r"(b1));
}

// XOR-swizzled smem offset for [rows][128 bf16] tiles (256 B rows, no padding).
#define SWZ(row, kbyte) ((unsigned)((row) * 256 + ((kbyte) ^ (((row) & 7) << 5))))

// ---------------- prelude: wsplit + xsplit + detect in ONE launch ------------
__global__ void prelude_kernel(const float* __restrict__ Wg,
                               const float* __restrict__ W1,
                               const float* __restrict__ W2,
                               const float* __restrict__ Wc,
                               const float* __restrict__ X,
                               const int* __restrict__ raw,
                               int N, int E, int nxb) {
    int b = blockIdx.x;
    if (b < 224) {                             // --- W split+transpose ---
        const float* W; int NOUT, off;
        if      (b < 64)  { W = Wg; NOUT = 128; off = 0;     }
        else if (b < 128) { W = W1; NOUT = 128; off = 16384; b -= 64;  }
        else if (b < 192) { W = W2; NOUT = 128; off = 32768; b -= 128; }
        else              { W = Wc; NOUT = 64;  off = 49152; b -= 192; }
        int i = b * 256 + threadIdx.x;
        if (i >= 128 * NOUT) return;
        int k = i / NOUT, n = i % NOUT;
        float v = __ldg(&W[i]);
        __nv_bfloat16 h = __float2bfloat16(v);
        __nv_bfloat16 l = __float2bfloat16(v - __bfloat162float(h));
        g_whT[off + n * 128 + k] = h;
        g_wlT[off + n * 128 + k] = l;
        return;
    }
    b -= 224;
    if (b < nxb) {                             // --- x split ---
        int i = b * 256 + threadIdx.x;
        if (i >= N * 32) return;
        float4 v = __ldg((const float4*)X + i);
        uint2 hi, lo;
        split2(v.x, v.y, hi.x, lo.x);
        split2(v.z, v.w, hi.y, lo.y);
        ((uint2*)g_sh)[i] = hi;
        ((uint2*)g_sl)[i] = lo;
        return;
    }
    // last block: index-width detect
    __shared__ int sh[256];
    int lim = (E >= 4096) ? 2048 : (E >> 1);
    int x = 0;
    for (int i = threadIdx.x; i < lim; i += 256) x |= raw[2 * i + 1];
    sh[threadIdx.x] = x;
    __syncthreads();
    for (int s = 128; s > 0; s >>= 1) {
        if (threadIdx.x < s) sh[threadIdx.x] |= sh[threadIdx.x + s];
        __syncthreads();
    }
    if (threadIdx.x == 0) g_is64 = (sh[0] == 0) ? 1 : 0;
}

// ---------------- deg/rank: dst-only counting pass ---------------------------
// g_deg is zero on entry (module load / re-zeroed by scan1 last call).
__global__ void deg_rank_kernel(const int* __restrict__ rd, int E) {
    int i = blockIdx.x * blockDim.x + threadIdx.x;
    if (i >= E) return;
    int d = g_is64 ? rd[2 * i] : rd[i];
    g_rank[i] = atomicAdd(&g_deg[d], 1);
}

// ---------------- tensor-core GEMM: Y = X[N,128] @ W[128,NOUT] ---------------
template <int NOUT>
__global__ __launch_bounds__(256, 2) void gemm_mma_kernel(
        const __nv_bfloat16* __restrict__ Xh, const __nv_bfloat16* __restrict__ Xl,
        const __nv_bfloat16* __restrict__ WhT, const __nv_bfloat16* __restrict__ WlT,
        float* __restrict__ Y, int N) {
    constexpr int A_HI = 0;
    constexpr int A_LO = A_HI + 64 * 256;
    constexpr int B_HI = A_LO + 64 * 256;
    constexpr int B_LO = B_HI + NOUT * 256;
    constexpr int WNT  = NOUT / 4;
    constexpr int NB   = WNT / 8;
    extern __shared__ char sm[];

    const int tid  = threadIdx.x;
    const int wid  = tid >> 5;
    const int lane = tid & 31;
    const int row0 = blockIdx.x * 64;

#pragma unroll
    for (int i = 0; i < 4; i++) {
        int idx = tid + i * 256;
        int row = idx >> 4, kb16 = idx & 15;
        uint4 vh = make_uint4(0, 0, 0, 0), vl = make_uint4(0, 0, 0, 0);
        if (row0 + row < N) {
            vh = __ldg((const uint4*)Xh + (size_t)(row0 + row) * 16 + kb16);
            vl = __ldg((const uint4*)Xl + (size_t)(row0 + row) * 16 + kb16);
        }
        unsigned off = SWZ(row, kb16 * 16);
        *(uint4*)(sm + A_HI + off) = vh;
        *(uint4*)(sm + A_LO + off) = vl;
    }
#pragma unroll
    for (int i = 0; i < NOUT / 16; i++) {
        int idx = tid + i * 256;
        int n = idx >> 4, kb16 = idx & 15;
        uint4 vh = __ldg((const uint4*)WhT + n * 16 + kb16);
        uint4 vl = __ldg((const uint4*)WlT + n * 16 + kb16);
        unsigned off = SWZ(n, kb16 * 16);
        *(uint4*)(sm + B_HI + off) = vh;
        *(uint4*)(sm + B_LO + off) = vl;
    }
    __syncthreads();

    const int wm = wid & 1;
    const int wn = wid >> 1;
    const int lr = lane >> 2;
    const int lc = lane & 3;

    float acc[2][NB][4];
#pragma unroll
    for (int mi = 0; mi < 2; mi++)
#pragma unroll
        for (int ni = 0; ni < NB; ni++)
#pragma unroll
            for (int j = 0; j < 4; j++) acc[mi][ni][j] = 0.f;

#pragma unroll
    for (int k0 = 0; k0 < 128; k0 += 16) {
        const int kb = 2 * k0 + 4 * lc;
        uint32_t bh[NB][2], bl[NB][2];
#pragma unroll
        for (int ni = 0; ni < NB; ni++) {
            unsigned bo = SWZ(wn * WNT + ni * 8 + lr, kb);
            bh[ni][0] = *(const uint32_t*)(sm + B_HI + bo);
            bh[ni][1] = *(const uint32_t*)(sm + B_HI + bo + 16);
            bl[ni][0] = *(const uint32_t*)(sm + B_LO + bo);
            bl[ni][1] = *(const uint32_t*)(sm + B_LO + bo + 16);
        }
#pragma unroll
        for (int mi = 0; mi < 2; mi++) {
            unsigned ao = SWZ(wm * 32 + mi * 16 + lr, kb);
            uint32_t a0 = *(const uint32_t*)(sm + A_HI + ao);
            uint32_t a1 = *(const uint32_t*)(sm + A_HI + ao + 8 * 256);
            uint32_t a2 = *(const uint32_t*)(sm + A_HI + ao + 16);
            uint32_t a3 = *(const uint32_t*)(sm + A_HI + ao + 8 * 256 + 16);
            uint32_t l0 = *(const uint32_t*)(sm + A_LO + ao);
            uint32_t l1 = *(const uint32_t*)(sm + A_LO + ao + 8 * 256);
            uint32_t l2 = *(const uint32_t*)(sm + A_LO + ao + 16);
            uint32_t l3 = *(const uint32_t*)(sm + A_LO + ao + 8 * 256 + 16);
#pragma unroll
            for (int ni = 0; ni < NB; ni++) {
                mma16816(acc[mi][ni], a0, a1, a2, a3, bh[ni][0], bh[ni][1]);
                mma16816(acc[mi][ni], a0, a1, a2, a3, bl[ni][0], bl[ni][1]);
                mma16816(acc[mi][ni], l0, l1, l2, l3, bh[ni][0], bh[ni][1]);
            }
        }
    }

#pragma unroll
    for (int mi = 0; mi < 2; mi++) {
        int r0 = row0 + wm * 32 + mi * 16 + lr;
#pragma unroll
        for (int ni = 0; ni < NB; ni++) {
            int col = wn * WNT + ni * 8 + 2 * lc;
            if (r0 < N)
                *(float2*)&Y[(size_t)r0 * NOUT + col] =
                    make_float2(acc[mi][ni][0], acc[mi][ni][1]);
            if (r0 + 8 < N)
                *(float2*)&Y[(size_t)(r0 + 8) * NOUT + col] =
                    make_float2(acc[mi][ni][2], acc[mi][ni][3]);
        }
    }
}

// ---------------- el/er: per-node dot of h with attn vectors ----------------
__global__ void el_er_kernel(const float* __restrict__ al,
                             const float* __restrict__ ar, int N) {
    int gt = blockIdx.x * blockDim.x + threadIdx.x;
    int n = gt >> 5, lane = gt & 31;
    if (n >= N) return;
    float4 hv = __ldg((const float4*)g_h + (size_t)n * 32 + lane);
    float4 a  = __ldg((const float4*)al + lane);
    float4 b  = __ldg((const float4*)ar + lane);
    float sl = hv.x * a.x + hv.y * a.y + hv.z * a.z + hv.w * a.w;
    float sr = hv.x * b.x + hv.y * b.y + hv.z * b.z + hv.w * b.w;
#pragma unroll
    for (int o = 16; o; o >>= 1) {
        sl += __shfl_xor_sync(0xffffffffu, sl, o);
        sr += __shfl_xor_sync(0xffffffffu, sr, o);
    }
    if (lane == 0) { g_el[n] = sl; g_er[n] = sr; }
}

// ---------------- 2-launch parallel exclusive scan over degrees --------------
// scan1 consumes g_deg and re-zeroes it (self-restoring for the next call).
__global__ void scan1_kernel(int N) {
    __shared__ int sh[256];
    int t = threadIdx.x;
    int i = blockIdx.x * 256 + t;
    int v = 0;
    if (i < N) { v = g_deg[i]; g_deg[i] = 0; }
    sh[t] = v;
    __syncthreads();
#pragma unroll
    for (int off = 1; off < 256; off <<= 1) {
        int u = (t >= off) ? sh[t - off] : 0;
        __syncthreads();
        sh[t] += u;
        __syncthreads();
    }
    if (i < N) g_rowptr[i] = sh[t] - v;
    if (t == 255) g_bsum[blockIdx.x] = sh[255];
}

// scan2 folded in: every block locally scans the <=256 block sums and picks
// the exclusive prefix for its own block index (redundant but launch-free).
__global__ void scan3_kernel(int N, int E, int nb) {
    __shared__ int sh[256];
    int t = threadIdx.x;
    int v = (t < nb) ? g_bsum[t] : 0;
    sh[t] = v;
    __syncthreads();
#pragma unroll
    for (int off = 1; off < 256; off <<= 1) {
        int u = (t >= off) ? sh[t - off] : 0;
        __syncthreads();
        sh[t] += u;
        __syncthreads();
    }
    int base = (blockIdx.x > 0) ? sh[blockIdx.x - 1] : 0;   // exclusive prefix
    int i = blockIdx.x * 256 + t;
    if (i < N) g_rowptr[i] += base;
    if (i == 0) g_rowptr[N] = E;
}

// ---------------- fused edge pass: leaky+exp straight into CSR + esum --------
// No max-subtraction: |e| is O(8) for this model; expf clamped at 80 cannot
// overflow. CSR slot = rowptr[d] + rank[i]: no intermediate g_e, no 2nd pass.
__global__ void edge_scatter_kernel(const int* __restrict__ rs,
                                    const int* __restrict__ rd, int E) {
    int i = blockIdx.x * blockDim.x + threadIdx.x;
    if (i >= E) return;
    int s, d;
    if (g_is64) { s = rs[2 * i]; d = rd[2 * i]; }
    else        { s = rs[i];     d = rd[i];     }
    float e = g_el[s] + g_er[d];
    e = (e > 0.f) ? e : 0.2f * e;
    float ee = expf(fminf(e, 80.f));
    int p = g_rowptr[d] + g_rank[i];
    g_csrs[p] = s;
    g_csra[p] = ee;
    atomicAdd(&g_esum[d], ee);
}

// ---------------- SpMM (warp/row): row-scaled, writes split bf16 -------------
template <bool ELUACT>
__global__ void spmm128_kernel(const float* __restrict__ hp,
                               const float* __restrict__ bias, int N) {
    int gt = blockIdx.x * blockDim.x + threadIdx.x;
    int n = gt >> 5, lane = gt & 31;
    if (n >= N) return;
    int e  = g_rowptr[n];
    int e1 = g_rowptr[n + 1];
    float inv = (e1 > e) ? (1.f / g_esum[n]) : 0.f;
    float ax = 0.f, ay = 0.f, az = 0.f, aw = 0.f;
    const float4* hp4 = (const float4*)hp;
    for (; e + 4 <= e1; e += 4) {
        int   s0 = __ldg(&g_csrs[e]),     s1 = __ldg(&g_csrs[e + 1]);
        int   s2 = __ldg(&g_csrs[e + 2]), s3 = __ldg(&g_csrs[e + 3]);
        float a0 = __ldg(&g_csra[e]),     a1 = __ldg(&g_csra[e + 1]);
        float a2 = __ldg(&g_csra[e + 2]), a3 = __ldg(&g_csra[e + 3]);
        float4 v0 = __ldg(hp4 + (size_t)s0 * 32 + lane);
        float4 v1 = __ldg(hp4 + (size_t)s1 * 32 + lane);
        float4 v2 = __ldg(hp4 + (size_t)s2 * 32 + lane);
        float4 v3 = __ldg(hp4 + (size_t)s3 * 32 + lane);
        ax += a0 * v0.x + a1 * v1.x + a2 * v2.x + a3 * v3.x;
        ay += a0 * v0.y + a1 * v1.y + a2 * v2.y + a3 * v3.y;
        az += a0 * v0.z + a1 * v1.z + a2 * v2.z + a3 * v3.z;
        aw += a0 * v0.w + a1 * v1.w + a2 * v2.w + a3 * v3.w;
    }
    for (; e < e1; e++) {
        int   sA = __ldg(&g_csrs[e]);
        float aA = __ldg(&g_csra[e]);
        float4 vA = __ldg(hp4 + (size_t)sA * 32 + lane);
        ax += aA * vA.x; ay += aA * vA.y; az += aA * vA.z; aw += aA * vA.w;
    }
    ax *= inv; ay *= inv; az *= inv; aw *= inv;
    if (ELUACT) {
        ax = (ax > 0.f) ? ax : expm1f(ax);
        ay = (ay > 0.f) ? ay : expm1f(ay);
        az = (az > 0.f) ? az : expm1f(az);
        aw = (aw > 0.f) ? aw : expm1f(aw);
    } else {
        float4 b = __ldg((const float4*)bias + lane);
        ax += b.x; ay += b.y; az += b.z; aw += b.w;
    }
    uint2 hi, lo;
    split2(ax, ay, hi.x, lo.x);
    split2(az, aw, hi.y, lo.y);
    ((uint2*)g_sh)[(size_t)n * 32 + lane] = hi;
    ((uint2*)g_sl)[(size_t)n * 32 + lane] = lo;
}

// last consumer of g_esum: re-zeroes it for the next kernel_launch call.
__global__ void spmm64_kernel(const float* __restrict__ hp,
                              const float* __restrict__ bias,
                              float* __restrict__ out, int N) {
    int gt = blockIdx.x * blockDim.x + threadIdx.x;
    int n = gt >> 5, lane = gt & 31;
    if (n >= N) return;
    int e  = g_rowptr[n];
    int e1 = g_rowptr[n + 1];
    float inv = (e1 > e) ? (1.f / g_esum[n]) : 0.f;
    if (lane == 0) g_esum[n] = 0.f;
    float ax = 0.f, ay = 0.f;
    const float2* hp2 = (const float2*)hp;
    for (; e + 4 <= e1; e += 4) {
        int   s0 = __ldg(&g_csrs[e]),     s1 = __ldg(&g_csrs[e + 1]);
        int   s2 = __ldg(&g_csrs[e + 2]), s3 = __ldg(&g_csrs[e + 3]);
        float a0 = __ldg(&g_csra[e]),     a1 = __ldg(&g_csra[e + 1]);
        float a2 = __ldg(&g_csra[e + 2]), a3 = __ldg(&g_csra[e + 3]);
        float2 v0 = __ldg(hp2 + (size_t)s0 * 32 + lane);
        float2 v1 = __ldg(hp2 + (size_t)s1 * 32 + lane);
        float2 v2 = __ldg(hp2 + (size_t)s2 * 32 + lane);
        float2 v3 = __ldg(hp2 + (size_t)s3 * 32 + lane);
        ax += a0 * v0.x + a1 * v1.x + a2 * v2.x + a3 * v3.x;
        ay += a0 * v0.y + a1 * v1.y + a2 * v2.y + a3 * v3.y;
    }
    for (; e < e1; e++) {
        int   sA = __ldg(&g_csrs[e]);
        float aA = __ldg(&g_csra[e]);
        float2 vA = __ldg(hp2 + (size_t)sA * 32 + lane);
        ax += aA * vA.x; ay += aA * vA.y;
    }
    float2 b = __ldg((const float2*)bias + lane);
    float2 r; r.x = ax * inv + b.x; r.y = ay * inv + b.y;
    ((float2*)out)[(size_t)n * 32 + lane] = r;
}

// ---------------- launch -----------------------------------------------------
extern "C" void kernel_launch(void* const* d_in, const int* in_sizes, int n_in,
                              void* d_out, int out_size) {
    const float* x    = (const float*)d_in[0];
    const int*   srcR = (const int*)d_in[1];
    const int*   dstR = (const int*)d_in[2];
    const float* Wg   = (const float*)d_in[3];
    const float* al   = (const float*)d_in[4];
    const float* ar   = (const float*)d_in[5];
    const float* W1   = (const float*)d_in[6];
    const float* b1   = (const float*)d_in[7];
    const float* W2   = (const float*)d_in[8];
    const float* b2   = (const float*)d_in[9];
    const float* Wc   = (const float*)d_in[10];
    const float* bc   = (const float*)d_in[11];
    float* out = (float*)d_out;

    const int N = in_sizes[0] / HD;
    const int E = in_sizes[1];

    float *dh, *dt2;
    __nv_bfloat16 *dsh, *dsl, *dwh, *dwl;
    cudaGetSymbolAddress((void**)&dh,  g_h);
    cudaGetSymbolAddress((void**)&dt2, g_t2);
    cudaGetSymbolAddress((void**)&dsh, g_sh);
    cudaGetSymbolAddress((void**)&dsl, g_sl);
    cudaGetSymbolAddress((void**)&dwh, g_whT);
    cudaGetSymbolAddress((void**)&dwl, g_wlT);

    const int smem128 = 64 * 256 * 2 + 128 * 256 * 2;  // 98304 B
    const int smem64  = 64 * 256 * 2 + 64 * 256 * 2;   // 65536 B
    cudaFuncSetAttribute(gemm_mma_kernel<128>,
                         cudaFuncAttributeMaxDynamicSharedMemorySize, smem128);
    cudaFuncSetAttribute(gemm_mma_kernel<64>,
                         cudaFuncAttributeMaxDynamicSharedMemorySize, smem64);

    const int eb  = (E + 255) / 256;
    const int sb  = (N + 255) / 256;        // scan blocks
    const int nwb = (N * 32 + 255) / 256;   // warp-per-node kernels
    const int gb  = (N + 63) / 64;          // gemm blocks
    const int nxb = (N * 32 + 255) / 256;   // xsplit blocks

    // prelude: W split + x split + detect (no init pass needed)
    prelude_kernel<<<224 + nxb + 1, 256>>>(Wg, W1, W2, Wc, x, srcR, N, E, nxb);

    // CSR skeleton: deg/rank (dst only) -> scan (scan1 re-zeroes deg)
    deg_rank_kernel<<<eb, 256>>>(dstR, E);
    scan1_kernel<<<sb, 256>>>(N);
    scan3_kernel<<<sb, 256>>>(N, E, sb);

    // GAT: h = x @ W_gat ; el/er ; exp(e) straight into CSR + esum
    gemm_mma_kernel<128><<<gb, 256, smem128>>>(dsh, dsl, dwh, dwl, dh, N);
    el_er_kernel<<<nwb, 256>>>(al, ar, N);
    edge_scatter_kernel<<<eb, 256>>>(srcR, dstR, E);

    // h1 = elu((A @ h)/esum)        -> split bf16
    spmm128_kernel<true><<<nwb, 256>>>(dh, nullptr, N);

    // h2 = (A @ (h1 W1))/esum + b1  -> split bf16
    gemm_mma_kernel<128><<<gb, 256, smem128>>>(dsh, dsl, dwh + 16384, dwl + 16384, dt2, N);
    spmm128_kernel<false><<<nwb, 256>>>(dt2, b1, N);

    // h3 = ...                      -> split bf16
    gemm_mma_kernel<128><<<gb, 256, smem128>>>(dsh, dsl, dwh + 32768, dwl + 32768, dt2, N);
    spmm128_kernel<false><<<nwb, 256>>>(dt2, b2, N);

    // logits (spmm64 re-zeroes esum for the next call)
    gemm_mma_kernel<64><<<gb, 256, smem64>>>(dsh, dsl, dwh + 49152, dwl + 49152, dt2, N);
    spmm64_kernel<<<nwb, 256>>>(dt2, bc, out, N);
}

// round 15
// speedup vs baseline: 1.1061x; 1.1061x over previous
#include <cuda_runtime.h>
#include <cuda_bf16.h>
#include <math.h>
#include <stdint.h>

#define NN 50000
#define EE 800000
#define HD 128

// ---------------- scratch (device globals: no allocation allowed) -----------
__device__ __align__(16) float g_h [NN * HD];     // fp32 gemm out / gather src
__device__ __align__(16) float g_t2[NN * HD];     // fp32 gemm out / gather src
__device__ __align__(16) __nv_bfloat16 g_sh[NN * HD];  // split-hi gemm input
__device__ __align__(16) __nv_bfloat16 g_sl[NN * HD];  // split-lo gemm input
__device__ __align__(16) __nv_bfloat16 g_whT[2 * 128 * 128 + 64 * 128];
__device__ __align__(16) __nv_bfloat16 g_wlT[2 * 128 * 128 + 64 * 128];
__device__ float    g_bb[64];         // b2 @ Wc + bc
__device__ float    g_el[NN];
__device__ float    g_er[NN];
__device__ float    g_esum[NN];
__device__ float    g_e[EE];          // exp(e), unnormalized
__device__ int      g_rank[EE];       // edge rank within its dst row
__device__ int      g_deg[NN];
__device__ int      g_rowptr[NN + 1];
__device__ int      g_bsum[256];
__device__ int      g_csrs[EE];
__device__ float    g_csra[EE];       // exp(e) in CSR order (unnormalized)
__device__ int      g_is64;

// ---------------- helpers -----------------------------------------------------
__device__ __forceinline__ void split2(float a, float b, uint32_t& hi, uint32_t& lo) {
    __nv_bfloat16 h0 = __float2bfloat16(a);
    __nv_bfloat16 h1 = __float2bfloat16(b);
    __nv_bfloat16 l0 = __float2bfloat16(a - __bfloat162float(h0));
    __nv_bfloat16 l1 = __float2bfloat16(b - __bfloat162float(h1));
    hi = (uint32_t)__bfloat16_as_ushort(h0) | ((uint32_t)__bfloat16_as_ushort(h1) << 16);
    lo = (uint32_t)__bfloat16_as_ushort(l0) | ((uint32_t)__bfloat16_as_ushort(l1) << 16);
}

__device__ __forceinline__ void mma16816(float* c,
        uint32_t a0, uint32_t a1, uint32_t a2, uint32_t a3,
        uint32_t b0, uint32_t b1) {
    asm volatile(
        "mma.sync.aligned.m16n8k16.row.col.f32.bf16.bf16.f32 "
        "{%0,%1,%2,%3}, {%4,%5,%6,%7}, {%8,%9}, {%0,%1,%2,%3};"
        : "+f"(c[0]), "+f"(c[1]), "+f"(c[2]), "+f"(c[3])
        : "r"(a0), "r"(a1), "r"(a2), "r"(a3), "r"(b0), "r"(b1));
}

// XOR-swizzled smem offset for [rows][128 bf16] tiles (256 B rows, no padding).
#define SWZ(row, kbyte) ((unsigned)((row) * 256 + ((kbyte) ^ (((row) & 7) << 5))))

// ---------------- prelude: Wg/W1 split + M=W2@Wc split + bb + xsplit + ... ---
__global__ void prelude_kernel(const float* __restrict__ Wg,
                               const float* __restrict__ W1,
                               const float* __restrict__ W2,
                               const float* __restrict__ Wc,
                               const float* __restrict__ b2,
                               const float* __restrict__ bc,
                               const float* __restrict__ X,
                               const int* __restrict__ raw,
                               int N, int E, int nxb) {
    int b = blockIdx.x;
    if (b < 128) {                             // --- Wg / W1 split+transpose ---
        const float* W; int off;
        if (b < 64) { W = Wg; off = 0; }
        else        { W = W1; off = 16384; b -= 64; }
        int i = b * 256 + threadIdx.x;
        float v = __ldg(&W[i]);
        int k = i >> 7, n = i & 127;
        __nv_bfloat16 h = __float2bfloat16(v);
        __nv_bfloat16 l = __float2bfloat16(v - __bfloat162float(h));
        g_whT[off + n * 128 + k] = h;
        g_wlT[off + n * 128 + k] = l;
        return;
    }
    b -= 128;
    if (b < 32) {                              // --- M = W2 @ Wc, split+transpose ---
        int idx = b * 256 + threadIdx.x;       // 0..8191
        int k = idx >> 6, n = idx & 63;
        float s = 0.f;
#pragma unroll 4
        for (int j = 0; j < 128; j++)
            s += __ldg(&W2[k * 128 + j]) * __ldg(&Wc[j * 64 + n]);
        __nv_bfloat16 h = __float2bfloat16(s);
        __nv_bfloat16 l = __float2bfloat16(s - __bfloat162float(h));
        g_whT[32768 + n * 128 + k] = h;
        g_wlT[32768 + n * 128 + k] = l;
        return;
    }
    b -= 32;
    if (b == 0) {                              // --- bb = b2 @ Wc + bc ---
        int n = threadIdx.x;
        if (n < 64) {
            float s = 0.f;
#pragma unroll 4
            for (int j = 0; j < 128; j++)
                s += __ldg(&b2[j]) * __ldg(&Wc[j * 64 + n]);
            g_bb[n] = s + __ldg(&bc[n]);
        }
        return;
    }
    b -= 1;
    if (b < nxb) {                             // --- x split ---
        int i = b * 256 + threadIdx.x;
        if (i >= N * 32) return;
        float4 v = __ldg((const float4*)X + i);
        uint2 hi, lo;
        split2(v.x, v.y, hi.x, lo.x);
        split2(v.z, v.w, hi.y, lo.y);
        ((uint2*)g_sh)[i] = hi;
        ((uint2*)g_sl)[i] = lo;
        return;
    }
    b -= nxb;
    if (b == 0) {                              // --- index-width detect ---
        __shared__ int sh[256];
        int lim = (E >= 4096) ? 2048 : (E >> 1);
        int x = 0;
        for (int i = threadIdx.x; i < lim; i += 256) x |= raw[2 * i + 1];
        sh[threadIdx.x] = x;
        __syncthreads();
        for (int s = 128; s > 0; s >>= 1) {
            if (threadIdx.x < s) sh[threadIdx.x] |= sh[threadIdx.x + s];
            __syncthreads();
        }
        if (threadIdx.x == 0) g_is64 = (sh[0] == 0) ? 1 : 0;
        return;
    }
    b -= 1;                                    // --- init esum/deg ---
    int i = b * 256 + threadIdx.x;
    if (i < N) { g_esum[i] = 0.f; g_deg[i] = 0; }
}

// ---------------- tensor-core GEMM: Y = X[N,128] @ W[128,NOUT] ---------------
template <int NOUT>
__global__ __launch_bounds__(256, 2) void gemm_mma_kernel(
        const __nv_bfloat16* __restrict__ Xh, const __nv_bfloat16* __restrict__ Xl,
        const __nv_bfloat16* __restrict__ WhT, const __nv_bfloat16* __restrict__ WlT,
        float* __restrict__ Y, int N) {
    constexpr int A_HI = 0;
    constexpr int A_LO = A_HI + 64 * 256;
    constexpr int B_HI = A_LO + 64 * 256;
    constexpr int B_LO = B_HI + NOUT * 256;
    constexpr int WNT  = NOUT / 4;
    constexpr int NB   = WNT / 8;
    extern __shared__ char sm[];

    const int tid  = threadIdx.x;
    const int wid  = tid >> 5;
    const int lane = tid & 31;
    const int row0 = blockIdx.x * 64;

#pragma unroll
    for (int i = 0; i < 4; i++) {
        int idx = tid + i * 256;
        int row = idx >> 4, kb16 = idx & 15;
        uint4 vh = make_uint4(0, 0, 0, 0), vl = make_uint4(0, 0, 0, 0);
        if (row0 + row < N) {
            vh = __ldg((const uint4*)Xh + (size_t)(row0 + row) * 16 + kb16);
            vl = __ldg((const uint4*)Xl + (size_t)(row0 + row) * 16 + kb16);
        }
        unsigned off = SWZ(row, kb16 * 16);
        *(uint4*)(sm + A_HI + off) = vh;
        *(uint4*)(sm + A_LO + off) = vl;
    }
#pragma unroll
    for (int i = 0; i < NOUT / 16; i++) {
        int idx = tid + i * 256;
        int n = idx >> 4, kb16 = idx & 15;
        uint4 vh = __ldg((const uint4*)WhT + n * 16 + kb16);
        uint4 vl = __ldg((const uint4*)WlT + n * 16 + kb16);
        unsigned off = SWZ(n, kb16 * 16);
        *(uint4*)(sm + B_HI + off) = vh;
        *(uint4*)(sm + B_LO + off) = vl;
    }
    __syncthreads();

    const int wm = wid & 1;
    const int wn = wid >> 1;
    const int lr = lane >> 2;
    const int lc = lane & 3;

    float acc[2][NB][4];
#pragma unroll
    for (int mi = 0; mi < 2; mi++)
#pragma unroll
        for (int ni = 0; ni < NB; ni++)
#pragma unroll
            for (int j = 0; j < 4; j++) acc[mi][ni][j] = 0.f;

#pragma unroll
    for (int k0 = 0; k0 < 128; k0 += 16) {
        const int kb = 2 * k0 + 4 * lc;
        uint32_t bh[NB][2], bl[NB][2];
#pragma unroll
        for (int ni = 0; ni < NB; ni++) {
            unsigned bo = SWZ(wn * WNT + ni * 8 + lr, kb);
            bh[ni][0] = *(const uint32_t*)(sm + B_HI + bo);
            bh[ni][1] = *(const uint32_t*)(sm + B_HI + bo + 16);
            bl[ni][0] = *(const uint32_t*)(sm + B_LO + bo);
            bl[ni][1] = *(const uint32_t*)(sm + B_LO + bo + 16);
        }
#pragma unroll
        for (int mi = 0; mi < 2; mi++) {
            unsigned ao = SWZ(wm * 32 + mi * 16 + lr, kb);
            uint32_t a0 = *(const uint32_t*)(sm + A_HI + ao);
            uint32_t a1 = *(const uint32_t*)(sm + A_HI + ao + 8 * 256);
            uint32_t a2 = *(const uint32_t*)(sm + A_HI + ao + 16);
            uint32_t a3 = *(const uint32_t*)(sm + A_HI + ao + 8 * 256 + 16);
            uint32_t l0 = *(const uint32_t*)(sm + A_LO + ao);
            uint32_t l1 = *(const uint32_t*)(sm + A_LO + ao + 8 * 256);
            uint32_t l2 = *(const uint32_t*)(sm + A_LO + ao + 16);
            uint32_t l3 = *(const uint32_t*)(sm + A_LO + ao + 8 * 256 + 16);
#pragma unroll
            for (int ni = 0; ni < NB; ni++) {
                mma16816(acc[mi][ni], a0, a1, a2, a3, bh[ni][0], bh[ni][1]);
                mma16816(acc[mi][ni], a0, a1, a2, a3, bl[ni][0], bl[ni][1]);
                mma16816(acc[mi][ni], l0, l1, l2, l3, bh[ni][0], bh[ni][1]);
            }
        }
    }

#pragma unroll
    for (int mi = 0; mi < 2; mi++) {
        int r0 = row0 + wm * 32 + mi * 16 + lr;
#pragma unroll
        for (int ni = 0; ni < NB; ni++) {
            int col = wn * WNT + ni * 8 + 2 * lc;
            if (r0 < N)
                *(float2*)&Y[(size_t)r0 * NOUT + col] =
                    make_float2(acc[mi][ni][0], acc[mi][ni][1]);
            if (r0 + 8 < N)
                *(float2*)&Y[(size_t)(r0 + 8) * NOUT + col] =
                    make_float2(acc[mi][ni][2], acc[mi][ni][3]);
        }
    }
}

// ---------------- el/er: per-node dot of h with attn vectors ----------------
__global__ void el_er_kernel(const float* __restrict__ al,
                             const float* __restrict__ ar, int N) {
    int gt = blockIdx.x * blockDim.x + threadIdx.x;
    int n = gt >> 5, lane = gt & 31;
    if (n >= N) return;
    float4 hv = __ldg((const float4*)g_h + (size_t)n * 32 + lane);
    float4 a  = __ldg((const float4*)al + lane);
    float4 b  = __ldg((const float4*)ar + lane);
    float sl = hv.x * a.x + hv.y * a.y + hv.z * a.z + hv.w * a.w;
    float sr = hv.x * b.x + hv.y * b.y + hv.z * b.z + hv.w * b.w;
#pragma unroll
    for (int o = 16; o; o >>= 1) {
        sl += __shfl_xor_sync(0xffffffffu, sl, o);
        sr += __shfl_xor_sync(0xffffffffu, sr, o);
    }
    if (lane == 0) { g_el[n] = sl; g_er[n] = sr; }
}

// ---------------- fused edge pass: leaky + exp + sum + deg/rank --------------
__global__ void edge_pass_kernel(const int* __restrict__ rs,
                                 const int* __restrict__ rd, int E) {
    int i = blockIdx.x * blockDim.x + threadIdx.x;
    if (i >= E) return;
    int s, d;
    if (g_is64) { s = rs[2 * i]; d = rd[2 * i]; }
    else        { s = rs[i];     d = rd[i];     }
    float e = g_el[s] + g_er[d];
    e = (e > 0.f) ? e : 0.2f * e;
    float ee = expf(fminf(e, 80.f));
    g_e[i] = ee;
    g_rank[i] = atomicAdd(&g_deg[d], 1);
    atomicAdd(&g_esum[d], ee);
}

// ---------------- 2-launch parallel exclusive scan over degrees --------------
__global__ void scan1_kernel(int N) {
    __shared__ int sh[256];
    int t = threadIdx.x;
    int i = blockIdx.x * 256 + t;
    int v = (i < N) ? g_deg[i] : 0;
    sh[t] = v;
    __syncthreads();
#pragma unroll
    for (int off = 1; off < 256; off <<= 1) {
        int u = (t >= off) ? sh[t - off] : 0;
        __syncthreads();
        sh[t] += u;
        __syncthreads();
    }
    if (i < N) g_rowptr[i] = sh[t] - v;
    if (t == 255) g_bsum[blockIdx.x] = sh[255];
}

__global__ void scan3_kernel(int N, int E, int nb) {
    __shared__ int sh[256];
    int t = threadIdx.x;
    int v = (t < nb) ? g_bsum[t] : 0;
    sh[t] = v;
    __syncthreads();
#pragma unroll
    for (int off = 1; off < 256; off <<= 1) {
        int u = (t >= off) ? sh[t - off] : 0;
        __syncthreads();
        sh[t] += u;
        __syncthreads();
    }
    int base = (blockIdx.x > 0) ? sh[blockIdx.x - 1] : 0;
    int i = blockIdx.x * 256 + t;
    if (i < N) g_rowptr[i] += base;
    if (i == 0) g_rowptr[N] = E;
}

// ---------------- scatter: atomic-free CSR build -----------------------------
__global__ void scatter_kernel(const int* __restrict__ rs,
                               const int* __restrict__ rd, int E) {
    int i = blockIdx.x * blockDim.x + threadIdx.x;
    if (i >= E) return;
    int s, d;
    if (g_is64) { s = rs[2 * i]; d = rd[2 * i]; }
    else        { s = rs[i];     d = rd[i];     }
    int p = g_rowptr[d] + g_rank[i];
    g_csrs[p] = s;
    g_csra[p] = g_e[i];
}

// ---------------- SpMM (warp/row): row-scaled, writes split bf16 -------------
template <bool ELUACT>
__global__ void spmm128_kernel(const float* __restrict__ hp,
                               const float* __restrict__ bias, int N) {
    int gt = blockIdx.x * blockDim.x + threadIdx.x;
    int n = gt >> 5, lane = gt & 31;
    if (n >= N) return;
    int e  = g_rowptr[n];
    int e1 = g_rowptr[n + 1];
    float inv = (e1 > e) ? (1.f / g_esum[n]) : 0.f;
    float ax = 0.f, ay = 0.f, az = 0.f, aw = 0.f;
    const float4* hp4 = (const float4*)hp;
    for (; e + 4 <= e1; e += 4) {
        int   s0 = __ldg(&g_csrs[e]),     s1 = __ldg(&g_csrs[e + 1]);
        int   s2 = __ldg(&g_csrs[e + 2]), s3 = __ldg(&g_csrs[e + 3]);
        float a0 = __ldg(&g_csra[e]),     a1 = __ldg(&g_csra[e + 1]);
        float a2 = __ldg(&g_csra[e + 2]), a3 = __ldg(&g_csra[e + 3]);
        float4 v0 = __ldg(hp4 + (size_t)s0 * 32 + lane);
        float4 v1 = __ldg(hp4 + (size_t)s1 * 32 + lane);
        float4 v2 = __ldg(hp4 + (size_t)s2 * 32 + lane);
        float4 v3 = __ldg(hp4 + (size_t)s3 * 32 + lane);
        ax += a0 * v0.x + a1 * v1.x + a2 * v2.x + a3 * v3.x;
        ay += a0 * v0.y + a1 * v1.y + a2 * v2.y + a3 * v3.y;
        az += a0 * v0.z + a1 * v1.z + a2 * v2.z + a3 * v3.z;
        aw += a0 * v0.w + a1 * v1.w + a2 * v2.w + a3 * v3.w;
    }
    for (; e < e1; e++) {
        int   sA = __ldg(&g_csrs[e]);
        float aA = __ldg(&g_csra[e]);
        float4 vA = __ldg(hp4 + (size_t)sA * 32 + lane);
        ax += aA * vA.x; ay += aA * vA.y; az += aA * vA.z; aw += aA * vA.w;
    }
    ax *= inv; ay *= inv; az *= inv; aw *= inv;
    if (ELUACT) {
        ax = (ax > 0.f) ? ax : expm1f(ax);
        ay = (ay > 0.f) ? ay : expm1f(ay);
        az = (az > 0.f) ? az : expm1f(az);
        aw = (aw > 0.f) ? aw : expm1f(aw);
    } else {
        float4 b = __ldg((const float4*)bias + lane);
        ax += b.x; ay += b.y; az += b.z; aw += b.w;
    }
    uint2 hi, lo;
    split2(ax, ay, hi.x, lo.x);
    split2(az, aw, hi.y, lo.y);
    ((uint2*)g_sh)[(size_t)n * 32 + lane] = hi;
    ((uint2*)g_sl)[(size_t)n * 32 + lane] = lo;
}

// ---------------- SpMM 64-wide, fp32 out, no bias (middle aggregation) -------
__global__ void spmm64_mid_kernel(const float* __restrict__ hp,
                                  float* __restrict__ out, int N) {
    int gt = blockIdx.x * blockDim.x + threadIdx.x;
    int n = gt >> 5, lane = gt & 31;
    if (n >= N) return;
    int e  = g_rowptr[n];
    int e1 = g_rowptr[n + 1];
    float inv = (e1 > e) ? (1.f / g_esum[n]) : 0.f;
    float ax = 0.f, ay = 0.f;
    const float2* hp2 = (const float2*)hp;
    for (; e + 4 <= e1; e += 4) {
        int   s0 = __ldg(&g_csrs[e]),     s1 = __ldg(&g_csrs[e + 1]);
        int   s2 = __ldg(&g_csrs[e + 2]), s3 = __ldg(&g_csrs[e + 3]);
        float a0 = __ldg(&g_csra[e]),     a1 = __ldg(&g_csra[e + 1]);
        float a2 = __ldg(&g_csra[e + 2]), a3 = __ldg(&g_csra[e + 3]);
        float2 v0 = __ldg(hp2 + (size_t)s0 * 32 + lane);
        float2 v1 = __ldg(hp2 + (size_t)s1 * 32 + lane);
        float2 v2 = __ldg(hp2 + (size_t)s2 * 32 + lane);
        float2 v3 = __ldg(hp2 + (size_t)s3 * 32 + lane);
        ax += a0 * v0.x + a1 * v1.x + a2 * v2.x + a3 * v3.x;
        ay += a0 * v0.y + a1 * v1.y + a2 * v2.y + a3 * v3.y;
    }
    for (; e < e1; e++) {
        int   sA = __ldg(&g_csrs[e]);
        float aA = __ldg(&g_csra[e]);
        float2 vA = __ldg(hp2 + (size_t)sA * 32 + lane);
        ax += aA * vA.x; ay += aA * vA.y;
    }
    ((float2*)out)[(size_t)n * 32 + lane] = make_float2(ax * inv, ay * inv);
}

// ---------------- SpMM 64-wide final: bias = bb if row has edges else bc -----
__global__ void spmm64_final_kernel(const float* __restrict__ hp,
                                    const float* __restrict__ bc,
                                    float* __restrict__ out, int N) {
    int gt = blockIdx.x * blockDim.x + threadIdx.x;
    int n = gt >> 5, lane = gt & 31;
    if (n >= N) return;
    int e  = g_rowptr[n];
    int e1 = g_rowptr[n + 1];
    bool has = (e1 > e);
    float inv = has ? (1.f / g_esum[n]) : 0.f;
    float ax = 0.f, ay = 0.f;
    const float2* hp2 = (const float2*)hp;
    for (; e + 4 <= e1; e += 4) {
        int   s0 = __ldg(&g_csrs[e]),     s1 = __ldg(&g_csrs[e + 1]);
        int   s2 = __ldg(&g_csrs[e + 2]), s3 = __ldg(&g_csrs[e + 3]);
        float a0 = __ldg(&g_csra[e]),     a1 = __ldg(&g_csra[e + 1]);
        float a2 = __ldg(&g_csra[e + 2]), a3 = __ldg(&g_csra[e + 3]);
        float2 v0 = __ldg(hp2 + (size_t)s0 * 32 + lane);
        float2 v1 = __ldg(hp2 + (size_t)s1 * 32 + lane);
        float2 v2 = __ldg(hp2 + (size_t)s2 * 32 + lane);
        float2 v3 = __ldg(hp2 + (size_t)s3 * 32 + lane);
        ax += a0 * v0.x + a1 * v1.x + a2 * v2.x + a3 * v3.x;
        ay += a0 * v0.y + a1 * v1.y + a2 * v2.y + a3 * v3.y;
    }
    for (; e < e1; e++) {
        int   sA = __ldg(&g_csrs[e]);
        float aA = __ldg(&g_csra[e]);
        float2 vA = __ldg(hp2 + (size_t)sA * 32 + lane);
        ax += aA * vA.x; ay += aA * vA.y;
    }
    float2 bv;
    if (has) bv = *(const float2*)&g_bb[lane * 2];          // b2@Wc + bc
    else     bv = __ldg((const float2*)bc + lane);          // isolated: bc
    ((float2*)out)[(size_t)n * 32 + lane] =
        make_float2(ax * inv + bv.x, ay * inv + bv.y);
}

// ---------------- launch -----------------------------------------------------
extern "C" void kernel_launch(void* const* d_in, const int* in_sizes, int n_in,
                              void* d_out, int out_size) {
    const float* x    = (const float*)d_in[0];
    const int*   srcR = (const int*)d_in[1];
    const int*   dstR = (const int*)d_in[2];
    const float* Wg   = (const float*)d_in[3];
    const float* al   = (const float*)d_in[4];
    const float* ar   = (const float*)d_in[5];
    const float* W1   = (const float*)d_in[6];
    const float* b1   = (const float*)d_in[7];
    const float* W2   = (const float*)d_in[8];
    const float* b2   = (const float*)d_in[9];
    const float* Wc   = (const float*)d_in[10];
    const float* bc   = (const float*)d_in[11];
    float* out = (float*)d_out;

    const int N = in_sizes[0] / HD;
    const int E = in_sizes[1];

    float *dh, *dt2;
    __nv_bfloat16 *dsh, *dsl, *dwh, *dwl;
    cudaGetSymbolAddress((void**)&dh,  g_h);
    cudaGetSymbolAddress((void**)&dt2, g_t2);
    cudaGetSymbolAddress((void**)&dsh, g_sh);
    cudaGetSymbolAddress((void**)&dsl, g_sl);
    cudaGetSymbolAddress((void**)&dwh, g_whT);
    cudaGetSymbolAddress((void**)&dwl, g_wlT);

    const int smem128 = 64 * 256 * 2 + 128 * 256 * 2;  // 98304 B
    const int smem64  = 64 * 256 * 2 + 64 * 256 * 2;   // 65536 B
    cudaFuncSetAttribute(gemm_mma_kernel<128>,
                         cudaFuncAttributeMaxDynamicSharedMemorySize, smem128);
    cudaFuncSetAttribute(gemm_mma_kernel<64>,
                         cudaFuncAttributeMaxDynamicSharedMemorySize, smem64);

    const int eb  = (E + 255) / 256;
    const int sb  = (N + 255) / 256;        // scan/init blocks
    const int nwb = (N * 32 + 255) / 256;   // warp-per-node kernels
    const int gb  = (N + 63) / 64;          // gemm blocks
    const int nxb = (N * 32 + 255) / 256;   // xsplit blocks

    // prelude: Wg/W1 split (128) + M=W2@Wc split (32) + bb (1) + xsplit + detect + init
    prelude_kernel<<<128 + 32 + 1 + nxb + 1 + sb, 256>>>(
        Wg, W1, W2, Wc, b2, bc, x, srcR, N, E, nxb);

    // GAT: h = x @ W_gat ; el/er ; fused edge pass (exp/sum/deg+rank)
    gemm_mma_kernel<128><<<gb, 256, smem128>>>(dsh, dsl, dwh, dwl, dh, N);
    el_er_kernel<<<nwb, 256>>>(al, ar, N);
    edge_pass_kernel<<<eb, 256>>>(srcR, dstR, E);

    // CSR over dst: 2-launch scan -> atomic-free scatter
    scan1_kernel<<<sb, 256>>>(N);
    scan3_kernel<<<sb, 256>>>(N, E, sb);
    scatter_kernel<<<eb, 256>>>(srcR, dstR, E);

    // h1 = elu((A @ h)/esum)        -> split bf16
    spmm128_kernel<true><<<nwb, 256>>>(dh, nullptr, N);

    // h2 = (A @ (h1 W1))/esum + b1  -> split bf16
    gemm_mma_kernel<128><<<gb, 256, smem128>>>(dsh, dsl, dwh + 16384, dwl + 16384, dt2, N);
    spmm128_kernel<false><<<nwb, 256>>>(dt2, b1, N);

    // Collapsed linear tail:  logits = A@(A@(h2 M)) + bb,  M = W2@Wc
    gemm_mma_kernel<64><<<gb, 256, smem64>>>(dsh, dsl, dwh + 32768, dwl + 32768, dt2, N);
    spmm64_mid_kernel<<<nwb, 256>>>(dt2, dh, N);
    spmm64_final_kernel<<<nwb, 256>>>(dh, bc, out, N);
}

// round 16
// speedup vs baseline: 1.2080x; 1.0922x over previous
#include <cuda_runtime.h>
#include <cuda_bf16.h>
#include <math.h>
#include <stdint.h>

#define NN 50000
#define EE 800000
#define HD 128

// ---------------- scratch (device globals: no allocation allowed) -----------
__device__ __align__(16) float g_h [NN * HD];     // fp32 gemm out / gather src
__device__ __align__(16) float g_t2[NN * HD];     // fp32 stage out / gather src
__device__ __align__(16) __nv_bfloat16 g_sh[NN * HD];  // split-hi gemm input
__device__ __align__(16) __nv_bfloat16 g_sl[NN * HD];  // split-lo gemm input
__device__ __align__(16) __nv_bfloat16 g_whT[128 * 128 + 64 * 128];
__device__ __align__(16) __nv_bfloat16 g_wlT[128 * 128 + 64 * 128];
__device__ float    g_M[128 * 64];    // W2 @ Wc (fp32)
__device__ float    g_bb[64];         // b2 @ Wc + bc
__device__ float    g_b1M[64];        // b1 @ M
__device__ float    g_el[NN];
__device__ float    g_er[NN];
__device__ float    g_esum[NN];
__device__ float    g_e[EE];          // exp(e), unnormalized
__device__ int      g_rank[EE];       // edge rank within its dst row
__device__ int      g_deg[NN];
__device__ int      g_rowptr[NN + 1];
__device__ int      g_bsum[256];
__device__ int      g_csrs[EE];
__device__ float    g_csra[EE];       // exp(e) in CSR order (unnormalized)
__device__ int      g_is64;

// ---------------- helpers -----------------------------------------------------
__device__ __forceinline__ void split2(float a, float b, uint32_t& hi, uint32_t& lo) {
    __nv_bfloat16 h0 = __float2bfloat16(a);
    __nv_bfloat16 h1 = __float2bfloat16(b);
    __nv_bfloat16 l0 = __float2bfloat16(a - __bfloat162float(h0));
    __nv_bfloat16 l1 = __float2bfloat16(b - __bfloat162float(h1));
    hi = (uint32_t)__bfloat16_as_ushort(h0) | ((uint32_t)__bfloat16_as_ushort(h1) << 16);
    lo = (uint32_t)__bfloat16_as_ushort(l0) | ((uint32_t)__bfloat16_as_ushort(l1) << 16);
}

__device__ __forceinline__ void mma16816(float* c,
        uint32_t a0, uint32_t a1, uint32_t a2, uint32_t a3,
        uint32_t b0, uint32_t b1) {
    asm volatile(
        "mma.sync.aligned.m16n8k16.row.col.f32.bf16.bf16.f32 "
        "{%0,%1,%2,%3}, {%4,%5,%6,%7}, {%8,%9}, {%0,%1,%2,%3};"
        : "+f"(c[0]), "+f"(c[1]), "+f"(c[2]), "+f"(c[3])
        : "r"(a0), "r"(a1), "r"(a2), "r"(a3), "r"(b0), "r"(b1));
}

// XOR-swizzled smem offset for [rows][128 bf16] tiles (256 B rows, no padding).
#define SWZ(row, kbyte) ((unsigned)((row) * 256 + ((kbyte) ^ (((row) & 7) << 5))))

// ---------------- prelude1: Wg split + M=W2@Wc + bb + xsplit + detect + init -
__global__ void prelude1_kernel(const float* __restrict__ Wg,
                                const float* __restrict__ W2,
                                const float* __restrict__ Wc,
                                const float* __restrict__ b2,
                                const float* __restrict__ bc,
                                const float* __restrict__ X,
                                const int* __restrict__ raw,
                                int N, int E, int nxb) {
    int b = blockIdx.x;
    if (b < 64) {                              // --- Wg split+transpose ---
        int i = b * 256 + threadIdx.x;
        float v = __ldg(&Wg[i]);
        int k = i >> 7, n = i & 127;
        __nv_bfloat16 h = __float2bfloat16(v);
        __nv_bfloat16 l = __float2bfloat16(v - __bfloat162float(h));
        g_whT[n * 128 + k] = h;
        g_wlT[n * 128 + k] = l;
        return;
    }
    b -= 64;
    if (b < 32) {                              // --- M = W2 @ Wc (fp32) ---
        int idx = b * 256 + threadIdx.x;       // 0..8191
        int k = idx >> 6, n = idx & 63;
        float s = 0.f;
#pragma unroll 4
        for (int j = 0; j < 128; j++)
            s += __ldg(&W2[k * 128 + j]) * __ldg(&Wc[j * 64 + n]);
        g_M[idx] = s;
        return;
    }
    b -= 32;
    if (b == 0) {                              // --- bb = b2 @ Wc + bc ---
        int n = threadIdx.x;
        if (n < 64) {
            float s = 0.f;
#pragma unroll 4
            for (int j = 0; j < 128; j++)
                s += __ldg(&b2[j]) * __ldg(&Wc[j * 64 + n]);
            g_bb[n] = s + __ldg(&bc[n]);
        }
        return;
    }
    b -= 1;
    if (b < nxb) {                             // --- x split ---
        int i = b * 256 + threadIdx.x;
        if (i >= N * 32) return;
        float4 v = __ldg((const float4*)X + i);
        uint2 hi, lo;
        split2(v.x, v.y, hi.x, lo.x);
        split2(v.z, v.w, hi.y, lo.y);
        ((uint2*)g_sh)[i] = hi;
        ((uint2*)g_sl)[i] = lo;
        return;
    }
    b -= nxb;
    if (b == 0) {                              // --- index-width detect ---
        __shared__ int sh[256];
        int lim = (E >= 4096) ? 2048 : (E >> 1);
        int x = 0;
        for (int i = threadIdx.x; i < lim; i += 256) x |= raw[2 * i + 1];
        sh[threadIdx.x] = x;
        __syncthreads();
        for (int s = 128; s > 0; s >>= 1) {
            if (threadIdx.x < s) sh[threadIdx.x] |= sh[threadIdx.x + s];
            __syncthreads();
        }
        if (threadIdx.x == 0) g_is64 = (sh[0] == 0) ? 1 : 0;
        return;
    }
    b -= 1;                                    // --- init esum/deg ---
    int i = b * 256 + threadIdx.x;
    if (i < N) { g_esum[i] = 0.f; g_deg[i] = 0; }
}

// ---------------- prelude2: W1M = W1 @ M split+transpose, b1M = b1 @ M -------
__global__ void prelude2_kernel(const float* __restrict__ W1,
                                const float* __restrict__ b1) {
    int b = blockIdx.x;
    if (b < 32) {
        int idx = b * 256 + threadIdx.x;       // 0..8191
        int k = idx >> 6, n = idx & 63;
        float s = 0.f;
#pragma unroll 4
        for (int j = 0; j < 128; j++)
            s += __ldg(&W1[k * 128 + j]) * g_M[j * 64 + n];
        __nv_bfloat16 h = __float2bfloat16(s);
        __nv_bfloat16 l = __float2bfloat16(s - __bfloat162float(h));
        g_whT[16384 + n * 128 + k] = h;
        g_wlT[16384 + n * 128 + k] = l;
        return;
    }
    int n = threadIdx.x;                       // --- b1M ---
    if (n < 64) {
        float s = 0.f;
#pragma unroll 4
        for (int j = 0; j < 128; j++)
            s += __ldg(&b1[j]) * g_M[j * 64 + n];
        g_b1M[n] = s;
    }
}

// ---------------- tensor-core GEMM: Y = X[N,128] @ W[128,NOUT] (+ bias) ------
template <int NOUT>
__global__ __launch_bounds__(256, 2) void gemm_mma_kernel(
        const __nv_bfloat16* __restrict__ Xh, const __nv_bfloat16* __restrict__ Xl,
        const __nv_bfloat16* __restrict__ WhT, const __nv_bfloat16* __restrict__ WlT,
        const float* __restrict__ bias, float* __restrict__ Y, int N) {
    constexpr int A_HI = 0;
    constexpr int A_LO = A_HI + 64 * 256;
    constexpr int B_HI = A_LO + 64 * 256;
    constexpr int B_LO = B_HI + NOUT * 256;
    constexpr int WNT  = NOUT / 4;
    constexpr int NB   = WNT / 8;
    extern __shared__ char sm[];

    const int tid  = threadIdx.x;
    const int wid  = tid >> 5;
    const int lane = tid & 31;
    const int row0 = blockIdx.x * 64;

#pragma unroll
    for (int i = 0; i < 4; i++) {
        int idx = tid + i * 256;
        int row = idx >> 4, kb16 = idx & 15;
        uint4 vh = make_uint4(0, 0, 0, 0), vl = make_uint4(0, 0, 0, 0);
        if (row0 + row < N) {
            vh = __ldg((const uint4*)Xh + (size_t)(row0 + row) * 16 + kb16);
            vl = __ldg((const uint4*)Xl + (size_t)(row0 + row) * 16 + kb16);
        }
        unsigned off = SWZ(row, kb16 * 16);
        *(uint4*)(sm + A_HI + off) = vh;
        *(uint4*)(sm + A_LO + off) = vl;
    }
#pragma unroll
    for (int i = 0; i < NOUT / 16; i++) {
        int idx = tid + i * 256;
        int n = idx >> 4, kb16 = idx & 15;
        uint4 vh = __ldg((const uint4*)WhT + n * 16 + kb16);
        uint4 vl = __ldg((const uint4*)WlT + n * 16 + kb16);
        unsigned off = SWZ(n, kb16 * 16);
        *(uint4*)(sm + B_HI + off) = vh;
        *(uint4*)(sm + B_LO + off) = vl;
    }
    __syncthreads();

    const int wm = wid & 1;
    const int wn = wid >> 1;
    const int lr = lane >> 2;
    const int lc = lane & 3;

    float acc[2][NB][4];
#pragma unroll
    for (int mi = 0; mi < 2; mi++)
#pragma unroll
        for (int ni = 0; ni < NB; ni++)
#pragma unroll
            for (int j = 0; j < 4; j++) acc[mi][ni][j] = 0.f;

#pragma unroll
    for (int k0 = 0; k0 < 128; k0 += 16) {
        const int kb = 2 * k0 + 4 * lc;
        uint32_t bh[NB][2], bl[NB][2];
#pragma unroll
        for (int ni = 0; ni < NB; ni++) {
            unsigned bo = SWZ(wn * WNT + ni * 8 + lr, kb);
            bh[ni][0] = *(const uint32_t*)(sm + B_HI + bo);
            bh[ni][1] = *(const uint32_t*)(sm + B_HI + bo + 16);
            bl[ni][0] = *(const uint32_t*)(sm + B_LO + bo);
            bl[ni][1] = *(const uint32_t*)(sm + B_LO + bo + 16);
        }
#pragma unroll
        for (int mi = 0; mi < 2; mi++) {
            unsigned ao = SWZ(wm * 32 + mi * 16 + lr, kb);
            uint32_t a0 = *(const uint32_t*)(sm + A_HI + ao);
            uint32_t a1 = *(const uint32_t*)(sm + A_HI + ao + 8 * 256);
            uint32_t a2 = *(const uint32_t*)(sm + A_HI + ao + 16);
            uint32_t a3 = *(const uint32_t*)(sm + A_HI + ao + 8 * 256 + 16);
            uint32_t l0 = *(const uint32_t*)(sm + A_LO + ao);
            uint32_t l1 = *(const uint32_t*)(sm + A_LO + ao + 8 * 256);
            uint32_t l2 = *(const uint32_t*)(sm + A_LO + ao + 16);
            uint32_t l3 = *(const uint32_t*)(sm + A_LO + ao + 8 * 256 + 16);
#pragma unroll
            for (int ni = 0; ni < NB; ni++) {
                mma16816(acc[mi][ni], a0, a1, a2, a3, bh[ni][0], bh[ni][1]);
                mma16816(acc[mi][ni], a0, a1, a2, a3, bl[ni][0], bl[ni][1]);
                mma16816(acc[mi][ni], l0, l1, l2, l3, bh[ni][0], bh[ni][1]);
            }
        }
    }

#pragma unroll
    for (int mi = 0; mi < 2; mi++) {
        int r0 = row0 + wm * 32 + mi * 16 + lr;
#pragma unroll
        for (int ni = 0; ni < NB; ni++) {
            int col = wn * WNT + ni * 8 + 2 * lc;
            float2 bv = make_float2(0.f, 0.f);
            if (bias) bv = __ldg((const float2*)&bias[col]);
            if (r0 < N)
                *(float2*)&Y[(size_t)r0 * NOUT + col] =
                    make_float2(acc[mi][ni][0] + bv.x, acc[mi][ni][1] + bv.y);
            if (r0 + 8 < N)
                *(float2*)&Y[(size_t)(r0 + 8) * NOUT + col] =
                    make_float2(acc[mi][ni][2] + bv.x, acc[mi][ni][3] + bv.y);
        }
    }
}

// ---------------- el/er: per-node dot of h with attn vectors ----------------
__global__ void el_er_kernel(const float* __restrict__ al,
                             const float* __restrict__ ar, int N) {
    int gt = blockIdx.x * blockDim.x + threadIdx.x;
    int n = gt >> 5, lane = gt & 31;
    if (n >= N) return;
    float4 hv = __ldg((const float4*)g_h + (size_t)n * 32 + lane);
    float4 a  = __ldg((const float4*)al + lane);
    float4 b  = __ldg((const float4*)ar + lane);
    float sl = hv.x * a.x + hv.y * a.y + hv.z * a.z + hv.w * a.w;
    float sr = hv.x * b.x + hv.y * b.y + hv.z * b.z + hv.w * b.w;
#pragma unroll
    for (int o = 16; o; o >>= 1) {
        sl += __shfl_xor_sync(0xffffffffu, sl, o);
        sr += __shfl_xor_sync(0xffffffffu, sr, o);
    }
    if (lane == 0) { g_el[n] = sl; g_er[n] = sr; }
}

// ---------------- fused edge pass: leaky + exp + sum + deg/rank --------------
__global__ void edge_pass_kernel(const int* __restrict__ rs,
                                 const int* __restrict__ rd, int E) {
    int i = blockIdx.x * blockDim.x + threadIdx.x;
    if (i >= E) return;
    int s, d;
    if (g_is64) { s = rs[2 * i]; d = rd[2 * i]; }
    else        { s = rs[i];     d = rd[i];     }
    float e = g_el[s] + g_er[d];
    e = (e > 0.f) ? e : 0.2f * e;
    float ee = expf(fminf(e, 80.f));
    g_e[i] = ee;
    g_rank[i] = atomicAdd(&g_deg[d], 1);
    atomicAdd(&g_esum[d], ee);
}

// ---------------- 2-launch parallel exclusive scan over degrees --------------
__global__ void scan1_kernel(int N) {
    __shared__ int sh[256];
    int t = threadIdx.x;
    int i = blockIdx.x * 256 + t;
    int v = (i < N) ? g_deg[i] : 0;
    sh[t] = v;
    __syncthreads();
#pragma unroll
    for (int off = 1; off < 256; off <<= 1) {
        int u = (t >= off) ? sh[t - off] : 0;
        __syncthreads();
        sh[t] += u;
        __syncthreads();
    }
    if (i < N) g_rowptr[i] = sh[t] - v;
    if (t == 255) g_bsum[blockIdx.x] = sh[255];
}

__global__ void scan3_kernel(int N, int E, int nb) {
    __shared__ int sh[256];
    int t = threadIdx.x;
    int v = (t < nb) ? g_bsum[t] : 0;
    sh[t] = v;
    __syncthreads();
#pragma unroll
    for (int off = 1; off < 256; off <<= 1) {
        int u = (t >= off) ? sh[t - off] : 0;
        __syncthreads();
        sh[t] += u;
        __syncthreads();
    }
    int base = (blockIdx.x > 0) ? sh[blockIdx.x - 1] : 0;
    int i = blockIdx.x * 256 + t;
    if (i < N) g_rowptr[i] += base;
    if (i == 0) g_rowptr[N] = E;
}

// ---------------- scatter: atomic-free CSR build -----------------------------
__global__ void scatter_kernel(const int* __restrict__ rs,
                               const int* __restrict__ rd, int E) {
    int i = blockIdx.x * blockDim.x + threadIdx.x;
    if (i >= E) return;
    int s, d;
    if (g_is64) { s = rs[2 * i]; d = rd[2 * i]; }
    else        { s = rs[i];     d = rd[i];     }
    int p = g_rowptr[d] + g_rank[i];
    g_csrs[p] = s;
    g_csra[p] = g_e[i];
}

// ---------------- SpMM 128-wide + ELU, fp32 out ------------------------------
__global__ void spmm128_elu_kernel(const float* __restrict__ hp,
                                   float* __restrict__ out, int N) {
    int gt = blockIdx.x * blockDim.x + threadIdx.x;
    int n = gt >> 5, lane = gt & 31;
    if (n >= N) return;
    int e  = g_rowptr[n];
    int e1 = g_rowptr[n + 1];
    float inv = (e1 > e) ? (1.f / g_esum[n]) : 0.f;
    float ax = 0.f, ay = 0.f, az = 0.f, aw = 0.f;
    const float4* hp4 = (const float4*)hp;
    for (; e + 4 <= e1; e += 4) {
        int   s0 = __ldg(&g_csrs[e]),     s1 = __ldg(&g_csrs[e + 1]);
        int   s2 = __ldg(&g_csrs[e + 2]), s3 = __ldg(&g_csrs[e + 3]);
        float a0 = __ldg(&g_csra[e]),     a1 = __ldg(&g_csra[e + 1]);
        float a2 = __ldg(&g_csra[e + 2]), a3 = __ldg(&g_csra[e + 3]);
        float4 v0 = __ldg(hp4 + (size_t)s0 * 32 + lane);
        float4 v1 = __ldg(hp4 + (size_t)s1 * 32 + lane);
        float4 v2 = __ldg(hp4 + (size_t)s2 * 32 + lane);
        float4 v3 = __ldg(hp4 + (size_t)s3 * 32 + lane);
        ax += a0 * v0.x + a1 * v1.x + a2 * v2.x + a3 * v3.x;
        ay += a0 * v0.y + a1 * v1.y + a2 * v2.y + a3 * v3.y;
        az += a0 * v0.z + a1 * v1.z + a2 * v2.z + a3 * v3.z;
        aw += a0 * v0.w + a1 * v1.w + a2 * v2.w + a3 * v3.w;
    }
    for (; e < e1; e++) {
        int   sA = __ldg(&g_csrs[e]);
        float aA = __ldg(&g_csra[e]);
        float4 vA = __ldg(hp4 + (size_t)sA * 32 + lane);
        ax += aA * vA.x; ay += aA * vA.y; az += aA * vA.z; aw += aA * vA.w;
    }
    ax *= inv; ay *= inv; az *= inv; aw *= inv;
    float4 r;
    r.x = (ax > 0.f) ? ax : expm1f(ax);
    r.y = (ay > 0.f) ? ay : expm1f(ay);
    r.z = (az > 0.f) ? az : expm1f(az);
    r.w = (aw > 0.f) ? aw : expm1f(aw);
    ((float4*)out)[(size_t)n * 32 + lane] = r;
}

// ---------------- SpMM 128-wide, writes split bf16 (no bias/act) -------------
__global__ void spmm128_split_kernel(const float* __restrict__ hp, int N) {
    int gt = blockIdx.x * blockDim.x + threadIdx.x;
    int n = gt >> 5, lane = gt & 31;
    if (n >= N) return;
    int e  = g_rowptr[n];
    int e1 = g_rowptr[n + 1];
    float inv = (e1 > e) ? (1.f / g_esum[n]) : 0.f;
    float ax = 0.f, ay = 0.f, az = 0.f, aw = 0.f;
    const float4* hp4 = (const float4*)hp;
    for (; e + 4 <= e1; e += 4) {
        int   s0 = __ldg(&g_csrs[e]),     s1 = __ldg(&g_csrs[e + 1]);
        int   s2 = __ldg(&g_csrs[e + 2]), s3 = __ldg(&g_csrs[e + 3]);
        float a0 = __ldg(&g_csra[e]),     a1 = __ldg(&g_csra[e + 1]);
        float a2 = __ldg(&g_csra[e + 2]), a3 = __ldg(&g_csra[e + 3]);
        float4 v0 = __ldg(hp4 + (size_t)s0 * 32 + lane);
        float4 v1 = __ldg(hp4 + (size_t)s1 * 32 + lane);
        float4 v2 = __ldg(hp4 + (size_t)s2 * 32 + lane);
        float4 v3 = __ldg(hp4 + (size_t)s3 * 32 + lane);
        ax += a0 * v0.x + a1 * v1.x + a2 * v2.x + a3 * v3.x;
        ay += a0 * v0.y + a1 * v1.y + a2 * v2.y + a3 * v3.y;
        az += a0 * v0.z + a1 * v1.z + a2 * v2.z + a3 * v3.z;
        aw += a0 * v0.w + a1 * v1.w + a2 * v2.w + a3 * v3.w;
    }
    for (; e < e1; e++) {
        int   sA = __ldg(&g_csrs[e]);
        float aA = __ldg(&g_csra[e]);
        float4 vA = __ldg(hp4 + (size_t)sA * 32 + lane);
        ax += aA * vA.x; ay += aA * vA.y; az += aA * vA.z; aw += aA * vA.w;
    }
    ax *= inv; ay *= inv; az *= inv; aw *= inv;
    uint2 hi, lo;
    split2(ax, ay, hi.x, lo.x);
    split2(az, aw, hi.y, lo.y);
    ((uint2*)g_sh)[(size_t)n * 32 + lane] = hi;
    ((uint2*)g_sl)[(size_t)n * 32 + lane] = lo;
}

// ---------------- SpMM 64-wide, fp32 out, no bias (middle aggregation) -------
__global__ void spmm64_mid_kernel(const float* __restrict__ hp,
                                  float* __restrict__ out, int N) {
    int gt = blockIdx.x * blockDim.x + threadIdx.x;
    int n = gt >> 5, lane = gt & 31;
    if (n >= N) return;
    int e  = g_rowptr[n];
    int e1 = g_rowptr[n + 1];
    float inv = (e1 > e) ? (1.f / g_esum[n]) : 0.f;
    float ax = 0.f, ay = 0.f;
    const float2* hp2 = (const float2*)hp;
    for (; e + 4 <= e1; e += 4) {
        int   s0 = __ldg(&g_csrs[e]),     s1 = __ldg(&g_csrs[e + 1]);
        int   s2 = __ldg(&g_csrs[e + 2]), s3 = __ldg(&g_csrs[e + 3]);
        float a0 = __ldg(&g_csra[e]),     a1 = __ldg(&g_csra[e + 1]);
        float a2 = __ldg(&g_csra[e + 2]), a3 = __ldg(&g_csra[e + 3]);
        float2 v0 = __ldg(hp2 + (size_t)s0 * 32 + lane);
        float2 v1 = __ldg(hp2 + (size_t)s1 * 32 + lane);
        float2 v2 = __ldg(hp2 + (size_t)s2 * 32 + lane);
        float2 v3 = __ldg(hp2 + (size_t)s3 * 32 + lane);
        ax += a0 * v0.x + a1 * v1.x + a2 * v2.x + a3 * v3.x;
        ay += a0 * v0.y + a1 * v1.y + a2 * v2.y + a3 * v3.y;
    }
    for (; e < e1; e++) {
        int   sA = __ldg(&g_csrs[e]);
        float aA = __ldg(&g_csra[e]);
        float2 vA = __ldg(hp2 + (size_t)sA * 32 + lane);
        ax += aA * vA.x; ay += aA * vA.y;
    }
    ((float2*)out)[(size_t)n * 32 + lane] = make_float2(ax * inv, ay * inv);
}

// ---------------- SpMM 64-wide final: bias = bb if row has edges else bc -----
__global__ void spmm64_final_kernel(const float* __restrict__ hp,
                                    const float* __restrict__ bc,
                                    float* __restrict__ out, int N) {
    int gt = blockIdx.x * blockDim.x + threadIdx.x;
    int n = gt >> 5, lane = gt & 31;
    if (n >= N) return;
    int e  = g_rowptr[n];
    int e1 = g_rowptr[n + 1];
    bool has = (e1 > e);
    float inv = has ? (1.f / g_esum[n]) : 0.f;
    float ax = 0.f, ay = 0.f;
    const float2* hp2 = (const float2*)hp;
    for (; e + 4 <= e1; e += 4) {
        int   s0 = __ldg(&g_csrs[e]),     s1 = __ldg(&g_csrs[e + 1]);
        int   s2 = __ldg(&g_csrs[e + 2]), s3 = __ldg(&g_csrs[e + 3]);
        float a0 = __ldg(&g_csra[e]),     a1 = __ldg(&g_csra[e + 1]);
        float a2 = __ldg(&g_csra[e + 2]), a3 = __ldg(&g_csra[e + 3]);
        float2 v0 = __ldg(hp2 + (size_t)s0 * 32 + lane);
        float2 v1 = __ldg(hp2 + (size_t)s1 * 32 + lane);
        float2 v2 = __ldg(hp2 + (size_t)s2 * 32 + lane);
        float2 v3 = __ldg(hp2 + (size_t)s3 * 32 + lane);
        ax += a0 * v0.x + a1 * v1.x + a2 * v2.x + a3 * v3.x;
        ay += a0 * v0.y + a1 * v1.y + a2 * v2.y + a3 * v3.y;
    }
    for (; e < e1; e++) {
        int   sA = __ldg(&g_csrs[e]);
        float aA = __ldg(&g_csra[e]);
        float2 vA = __ldg(hp2 + (size_t)sA * 32 + lane);
        ax += aA * vA.x; ay += aA * vA.y;
    }
    float2 bv;
    if (has) bv = *(const float2*)&g_bb[lane * 2];          // b2@Wc + bc
    else     bv = __ldg((const float2*)bc + lane);          // isolated: bc
    ((float2*)out)[(size_t)n * 32 + lane] =
        make_float2(ax * inv + bv.x, ay * inv + bv.y);
}

// ---------------- launch -----------------------------------------------------
extern "C" void kernel_launch(void* const* d_in, const int* in_sizes, int n_in,
                              void* d_out, int out_size) {
    const float* x    = (const float*)d_in[0];
    const int*   srcR = (const int*)d_in[1];
    const int*   dstR = (const int*)d_in[2];
    const float* Wg   = (const float*)d_in[3];
    const float* al   = (const float*)d_in[4];
    const float* ar   = (const float*)d_in[5];
    const float* W1   = (const float*)d_in[6];
    const float* b1   = (const float*)d_in[7];
    const float* W2   = (const float*)d_in[8];
    const float* b2   = (const float*)d_in[9];
    const float* Wc   = (const float*)d_in[10];
    const float* bc   = (const float*)d_in[11];
    float* out = (float*)d_out;

    const int N = in_sizes[0] / HD;
    const int E = in_sizes[1];

    float *dh, *dt2, *db1M;
    __nv_bfloat16 *dsh, *dsl, *dwh, *dwl;
    cudaGetSymbolAddress((void**)&dh,   g_h);
    cudaGetSymbolAddress((void**)&dt2,  g_t2);
    cudaGetSymbolAddress((void**)&db1M, g_b1M);
    cudaGetSymbolAddress((void**)&dsh,  g_sh);
    cudaGetSymbolAddress((void**)&dsl,  g_sl);
    cudaGetSymbolAddress((void**)&dwh,  g_whT);
    cudaGetSymbolAddress((void**)&dwl,  g_wlT);

    const int smem128 = 64 * 256 * 2 + 128 * 256 * 2;  // 98304 B
    const int smem64  = 64 * 256 * 2 + 64 * 256 * 2;   // 65536 B
    cudaFuncSetAttribute(gemm_mma_kernel<128>,
                         cudaFuncAttributeMaxDynamicSharedMemorySize, smem128);
    cudaFuncSetAttribute(gemm_mma_kernel<64>,
                         cudaFuncAttributeMaxDynamicSharedMemorySize, smem64);

    const int eb  = (E + 255) / 256;
    const int sb  = (N + 255) / 256;        // scan/init blocks
    const int nwb = (N * 32 + 255) / 256;   // warp-per-node kernels
    const int gb  = (N + 63) / 64;          // gemm blocks
    const int nxb = (N * 32 + 255) / 256;   // xsplit blocks

    // prelude1: Wg split (64) + M (32) + bb (1) + xsplit + detect + init
    prelude1_kernel<<<64 + 32 + 1 + nxb + 1 + sb, 256>>>(
        Wg, W2, Wc, b2, bc, x, srcR, N, E, nxb);
    // prelude2: W1M split (32) + b1M (1)   [needs g_M from prelude1]
    prelude2_kernel<<<33, 256>>>(W1, b1);

    // GAT: h = x @ W_gat ; el/er ; fused edge pass (exp/sum/deg+rank)
    gemm_mma_kernel<128><<<gb, 256, smem128>>>(dsh, dsl, dwh, dwl, nullptr, dh, N);
    el_er_kernel<<<nwb, 256>>>(al, ar, N);
    edge_pass_kernel<<<eb, 256>>>(srcR, dstR, E);

    // CSR over dst: 2-launch scan -> atomic-free scatter
    scan1_kernel<<<sb, 256>>>(N);
    scan3_kernel<<<sb, 256>>>(N, E, sb);
    scatter_kernel<<<eb, 256>>>(srcR, dstR, E);

    // h1 = elu(P@h)                  (fp32)
    spmm128_elu_kernel<<<nwb, 256>>>(dh, dt2, N);
    // g  = P@h1                      (split bf16)
    spmm128_split_kernel<<<nwb, 256>>>(dt2, N);
    // v  = g @ W1M + b1M             (== h2 @ M, exact identity)
    gemm_mma_kernel<64><<<gb, 256, smem64>>>(dsh, dsl, dwh + 16384, dwl + 16384, db1M, dt2, N);
    // u  = P@v
    spmm64_mid_kernel<<<nwb, 256>>>(dt2, dh, N);
    // logits = P@u + (bb | bc)
    spmm64_final_kernel<<<nwb, 256>>>(dh, bc, out, N);
}

// round 17
// speedup vs baseline: 1.2224x; 1.0119x over previous
#include <cuda_runtime.h>
#include <cuda_bf16.h>
#include <math.h>
#include <stdint.h>

#define NN 50000
#define EE 800000
#define HD 128

// ---------------- scratch (device globals: no allocation allowed) -----------
__device__ __align__(16) float g_h [NN * HD];     // fp32 gemm out / gather src
__device__ __align__(16) float g_t2[NN * HD];     // fp32 stage out / gather src
__device__ __align__(16) __nv_bfloat16 g_sh[NN * HD];  // split-hi gemm input
__device__ __align__(16) __nv_bfloat16 g_sl[NN * HD];  // split-lo gemm input
__device__ __align__(16) __nv_bfloat16 g_whT[128 * 128 + 64 * 128];
__device__ __align__(16) __nv_bfloat16 g_wlT[128 * 128 + 64 * 128];
__device__ float    g_M[128 * 64];    // W2 @ Wc (fp32)
__device__ float    g_bb[64];         // b2 @ Wc + bc
__device__ float    g_b1M[64];        // b1 @ M
__device__ __align__(16) float g_wl[128];  // Wg @ attn_l
__device__ __align__(16) float g_wr[128];  // Wg @ attn_r
__device__ float    g_el[NN];
__device__ float    g_er[NN];
__device__ float    g_esum[NN];
__device__ float    g_e[EE];          // exp(e), unnormalized
__device__ int      g_rank[EE];       // edge rank within its dst row
__device__ int      g_deg[NN];
__device__ int      g_rowptr[NN + 1];
__device__ int      g_bsum[256];
__device__ int      g_csrs[EE];
__device__ float    g_csra[EE];       // exp(e) in CSR order (unnormalized)
__device__ int      g_is64;

// ---------------- helpers -----------------------------------------------------
__device__ __forceinline__ void split2(float a, float b, uint32_t& hi, uint32_t& lo) {
    __nv_bfloat16 h0 = __float2bfloat16(a);
    __nv_bfloat16 h1 = __float2bfloat16(b);
    __nv_bfloat16 l0 = __float2bfloat16(a - __bfloat162float(h0));
    __nv_bfloat16 l1 = __float2bfloat16(b - __bfloat162float(h1));
    hi = (uint32_t)__bfloat16_as_ushort(h0) | ((uint32_t)__bfloat16_as_ushort(h1) << 16);
    lo = (uint32_t)__bfloat16_as_ushort(l0) | ((uint32_t)__bfloat16_as_ushort(l1) << 16);
}

__device__ __forceinline__ void mma16816(float* c,
        uint32_t a0, uint32_t a1, uint32_t a2, uint32_t a3,
        uint32_t b0, uint32_t b1) {
    asm volatile(
        "mma.sync.aligned.m16n8k16.row.col.f32.bf16.bf16.f32 "
        "{%0,%1,%2,%3}, {%4,%5,%6,%7}, {%8,%9}, {%0,%1,%2,%3};"
        : "+f"(c[0]), "+f"(c[1]), "+f"(c[2]), "+f"(c[3])
        : "r"(a0), "r"(a1), "r"(a2), "r"(a3), "r"(b0), "r"(b1));
}

// XOR-swizzled smem offset for [rows][128 bf16] tiles (256 B rows, no padding).
#define SWZ(row, kbyte) ((unsigned)((row) * 256 + ((kbyte) ^ (((row) & 7) << 5))))

// ---------------- prelude1: Wg split + M + bb + wl/wr + detect + init --------
__global__ void prelude1_kernel(const float* __restrict__ Wg,
                                const float* __restrict__ W2,
                                const float* __restrict__ Wc,
                                const float* __restrict__ b2,
                                const float* __restrict__ bc,
                                const float* __restrict__ al,
                                const float* __restrict__ ar,
                                const int* __restrict__ raw,
                                int N, int E) {
    int b = blockIdx.x;
    if (b < 64) {                              // --- Wg split+transpose ---
        int i = b * 256 + threadIdx.x;
        float v = __ldg(&Wg[i]);
        int k = i >> 7, n = i & 127;
        __nv_bfloat16 h = __float2bfloat16(v);
        __nv_bfloat16 l = __float2bfloat16(v - __bfloat162float(h));
        g_whT[n * 128 + k] = h;
        g_wlT[n * 128 + k] = l;
        return;
    }
    b -= 64;
    if (b < 32) {                              // --- M = W2 @ Wc (fp32) ---
        int idx = b * 256 + threadIdx.x;       // 0..8191
        int k = idx >> 6, n = idx & 63;
        float s = 0.f;
#pragma unroll 4
        for (int j = 0; j < 128; j++)
            s += __ldg(&W2[k * 128 + j]) * __ldg(&Wc[j * 64 + n]);
        g_M[idx] = s;
        return;
    }
    b -= 32;
    if (b == 0) {                              // --- bb = b2 @ Wc + bc ---
        int n = threadIdx.x;
        if (n < 64) {
            float s = 0.f;
#pragma unroll 4
            for (int j = 0; j < 128; j++)
                s += __ldg(&b2[j]) * __ldg(&Wc[j * 64 + n]);
            g_bb[n] = s + __ldg(&bc[n]);
        }
        return;
    }
    b -= 1;
    if (b == 0) {                              // --- wl = Wg@al, wr = Wg@ar ---
        int t = threadIdx.x;
        if (t < 128) {
            float s = 0.f;
#pragma unroll 4
            for (int j = 0; j < 128; j++)
                s += __ldg(&Wg[t * 128 + j]) * __ldg(&al[j]);
            g_wl[t] = s;
        } else {
            int k = t - 128;
            float s = 0.f;
#pragma unroll 4
            for (int j = 0; j < 128; j++)
                s += __ldg(&Wg[k * 128 + j]) * __ldg(&ar[j]);
            g_wr[k] = s;
        }
        return;
    }
    b -= 1;
    if (b == 0) {                              // --- index-width detect ---
        __shared__ int sh[256];
        int lim = (E >= 4096) ? 2048 : (E >> 1);
        int x = 0;
        for (int i = threadIdx.x; i < lim; i += 256) x |= raw[2 * i + 1];
        sh[threadIdx.x] = x;
        __syncthreads();
        for (int s = 128; s > 0; s >>= 1) {
            if (threadIdx.x < s) sh[threadIdx.x] |= sh[threadIdx.x + s];
            __syncthreads();
        }
        if (threadIdx.x == 0) g_is64 = (sh[0] == 0) ? 1 : 0;
        return;
    }
    b -= 1;                                    // --- init esum/deg ---
    int i = b * 256 + threadIdx.x;
    if (i < N) { g_esum[i] = 0.f; g_deg[i] = 0; }
}

// ---------------- prelude2: W1M split + b1M + xsplit-with-el/er --------------
__global__ void prelude2_kernel(const float* __restrict__ W1,
                                const float* __restrict__ b1,
                                const float* __restrict__ X, int N) {
    int b = blockIdx.x;
    if (b < 32) {                              // --- W1M = W1 @ M split+transpose ---
        int idx = b * 256 + threadIdx.x;       // 0..8191
        int k = idx >> 6, n = idx & 63;
        float s = 0.f;
#pragma unroll 4
        for (int j = 0; j < 128; j++)
            s += __ldg(&W1[k * 128 + j]) * g_M[j * 64 + n];
        __nv_bfloat16 h = __float2bfloat16(s);
        __nv_bfloat16 l = __float2bfloat16(s - __bfloat162float(h));
        g_whT[16384 + n * 128 + k] = h;
        g_wlT[16384 + n * 128 + k] = l;
        return;
    }
    b -= 32;
    if (b == 0) {                              // --- b1M = b1 @ M ---
        int n = threadIdx.x;
        if (n < 64) {
            float s = 0.f;
#pragma unroll 4
            for (int j = 0; j < 128; j++)
                s += __ldg(&b1[j]) * g_M[j * 64 + n];
            g_b1M[n] = s;
        }
        return;
    }
    b -= 1;
    // --- x split + fused el/er (el = x·wl, er = x·wr) ---
    int i = b * 256 + threadIdx.x;             // float4 index
    if (i >= N * 32) return;
    int lane = i & 31;
    float4 v = __ldg((const float4*)X + i);
    uint2 hi, lo;
    split2(v.x, v.y, hi.x, lo.x);
    split2(v.z, v.w, hi.y, lo.y);
    ((uint2*)g_sh)[i] = hi;
    ((uint2*)g_sl)[i] = lo;
    float4 a = __ldg((const float4*)g_wl + lane);
    float4 c = __ldg((const float4*)g_wr + lane);
    float sl = v.x * a.x + v.y * a.y + v.z * a.z + v.w * a.w;
    float sr = v.x * c.x + v.y * c.y + v.z * c.z + v.w * c.w;
#pragma unroll
    for (int o = 16; o; o >>= 1) {
        sl += __shfl_xor_sync(0xffffffffu, sl, o);
        sr += __shfl_xor_sync(0xffffffffu, sr, o);
    }
    if (lane == 0) { g_el[i >> 5] = sl; g_er[i >> 5] = sr; }
}

// ---------------- tensor-core GEMM: Y = X[N,128] @ W[128,NOUT] (+ bias) ------
template <int NOUT>
__global__ __launch_bounds__(256, 2) void gemm_mma_kernel(
        const __nv_bfloat16* __restrict__ Xh, const __nv_bfloat16* __restrict__ Xl,
        const __nv_bfloat16* __restrict__ WhT, const __nv_bfloat16* __restrict__ WlT,
        const float* __restrict__ bias, float* __restrict__ Y, int N) {
    constexpr int A_HI = 0;
    constexpr int A_LO = A_HI + 64 * 256;
    constexpr int B_HI = A_LO + 64 * 256;
    constexpr int B_LO = B_HI + NOUT * 256;
    constexpr int WNT  = NOUT / 4;
    constexpr int NB   = WNT / 8;
    extern __shared__ char sm[];

    const int tid  = threadIdx.x;
    const int wid  = tid >> 5;
    const int lane = tid & 31;
    const int row0 = blockIdx.x * 64;

#pragma unroll
    for (int i = 0; i < 4; i++) {
        int idx = tid + i * 256;
        int row = idx >> 4, kb16 = idx & 15;
        uint4 vh = make_uint4(0, 0, 0, 0), vl = make_uint4(0, 0, 0, 0);
        if (row0 + row < N) {
            vh = __ldg((const uint4*)Xh + (size_t)(row0 + row) * 16 + kb16);
            vl = __ldg((const uint4*)Xl + (size_t)(row0 + row) * 16 + kb16);
        }
        unsigned off = SWZ(row, kb16 * 16);
        *(uint4*)(sm + A_HI + off) = vh;
        *(uint4*)(sm + A_LO + off) = vl;
    }
#pragma unroll
    for (int i = 0; i < NOUT / 16; i++) {
        int idx = tid + i * 256;
        int n = idx >> 4, kb16 = idx & 15;
        uint4 vh = __ldg((const uint4*)WhT + n * 16 + kb16);
        uint4 vl = __ldg((const uint4*)WlT + n * 16 + kb16);
        unsigned off = SWZ(n, kb16 * 16);
        *(uint4*)(sm + B_HI + off) = vh;
        *(uint4*)(sm + B_LO + off) = vl;
    }
    __syncthreads();

    const int wm = wid & 1;
    const int wn = wid >> 1;
    const int lr = lane >> 2;
    const int lc = lane & 3;

    float acc[2][NB][4];
#pragma unroll
    for (int mi = 0; mi < 2; mi++)
#pragma unroll
        for (int ni = 0; ni < NB; ni++)
#pragma unroll
            for (int j = 0; j < 4; j++) acc[mi][ni][j] = 0.f;

#pragma unroll
    for (int k0 = 0; k0 < 128; k0 += 16) {
        const int kb = 2 * k0 + 4 * lc;
        uint32_t bh[NB][2], bl[NB][2];
#pragma unroll
        for (int ni = 0; ni < NB; ni++) {
            unsigned bo = SWZ(wn * WNT + ni * 8 + lr, kb);
            bh[ni][0] = *(const uint32_t*)(sm + B_HI + bo);
            bh[ni][1] = *(const uint32_t*)(sm + B_HI + bo + 16);
            bl[ni][0] = *(const uint32_t*)(sm + B_LO + bo);
            bl[ni][1] = *(const uint32_t*)(sm + B_LO + bo + 16);
        }
#pragma unroll
        for (int mi = 0; mi < 2; mi++) {
            unsigned ao = SWZ(wm * 32 + mi * 16 + lr, kb);
            uint32_t a0 = *(const uint32_t*)(sm + A_HI + ao);
            uint32_t a1 = *(const uint32_t*)(sm + A_HI + ao + 8 * 256);
            uint32_t a2 = *(const uint32_t*)(sm + A_HI + ao + 16);
            uint32_t a3 = *(const uint32_t*)(sm + A_HI + ao + 8 * 256 + 16);
            uint32_t l0 = *(const uint32_t*)(sm + A_LO + ao);
            uint32_t l1 = *(const uint32_t*)(sm + A_LO + ao + 8 * 256);
            uint32_t l2 = *(const uint32_t*)(sm + A_LO + ao + 16);
            uint32_t l3 = *(const uint32_t*)(sm + A_LO + ao + 8 * 256 + 16);
#pragma unroll
            for (int ni = 0; ni < NB; ni++) {
                mma16816(acc[mi][ni], a0, a1, a2, a3, bh[ni][0], bh[ni][1]);
                mma16816(acc[mi][ni], a0, a1, a2, a3, bl[ni][0], bl[ni][1]);
                mma16816(acc[mi][ni], l0, l1, l2, l3, bh[ni][0], bh[ni][1]);
            }
        }
    }

#pragma unroll
    for (int mi = 0; mi < 2; mi++) {
        int r0 = row0 + wm * 32 + mi * 16 + lr;
#pragma unroll
        for (int ni = 0; ni < NB; ni++) {
            int col = wn * WNT + ni * 8 + 2 * lc;
            float2 bv = make_float2(0.f, 0.f);
            if (bias) bv = __ldg((const float2*)&bias[col]);
            if (r0 < N)
                *(float2*)&Y[(size_t)r0 * NOUT + col] =
                    make_float2(acc[mi][ni][0] + bv.x, acc[mi][ni][1] + bv.y);
            if (r0 + 8 < N)
                *(float2*)&Y[(size_t)(r0 + 8) * NOUT + col] =
                    make_float2(acc[mi][ni][2] + bv.x, acc[mi][ni][3] + bv.y);
        }
    }
}

// ---------------- fused edge pass: leaky + exp + sum + deg/rank --------------
__global__ void edge_pass_kernel(const int* __restrict__ rs,
                                 const int* __restrict__ rd, int E) {
    int i = blockIdx.x * blockDim.x + threadIdx.x;
    if (i >= E) return;
    int s, d;
    if (g_is64) { s = rs[2 * i]; d = rd[2 * i]; }
    else        { s = rs[i];     d = rd[i];     }
    float e = g_el[s] + g_er[d];
    e = (e > 0.f) ? e : 0.2f * e;
    float ee = expf(fminf(e, 80.f));
    g_e[i] = ee;
    g_rank[i] = atomicAdd(&g_deg[d], 1);
    atomicAdd(&g_esum[d], ee);
}

// ---------------- 2-launch parallel exclusive scan over degrees --------------
__global__ void scan1_kernel(int N) {
    __shared__ int sh[256];
    int t = threadIdx.x;
    int i = blockIdx.x * 256 + t;
    int v = (i < N) ? g_deg[i] : 0;
    sh[t] = v;
    __syncthreads();
#pragma unroll
    for (int off = 1; off < 256; off <<= 1) {
        int u = (t >= off) ? sh[t - off] : 0;
        __syncthreads();
        sh[t] += u;
        __syncthreads();
    }
    if (i < N) g_rowptr[i] = sh[t] - v;
    if (t == 255) g_bsum[blockIdx.x] = sh[255];
}

__global__ void scan3_kernel(int N, int E, int nb) {
    __shared__ int sh[256];
    int t = threadIdx.x;
    int v = (t < nb) ? g_bsum[t] : 0;
    sh[t] = v;
    __syncthreads();
#pragma unroll
    for (int off = 1; off < 256; off <<= 1) {
        int u = (t >= off) ? sh[t - off] : 0;
        __syncthreads();
        sh[t] += u;
        __syncthreads();
    }
    int base = (blockIdx.x > 0) ? sh[blockIdx.x - 1] : 0;
    int i = blockIdx.x * 256 + t;
    if (i < N) g_rowptr[i] += base;
    if (i == 0) g_rowptr[N] = E;
}

// ---------------- scatter: atomic-free CSR build -----------------------------
__global__ void scatter_kernel(const int* __restrict__ rs,
                               const int* __restrict__ rd, int E) {
    int i = blockIdx.x * blockDim.x + threadIdx.x;
    if (i >= E) return;
    int s, d;
    if (g_is64) { s = rs[2 * i]; d = rd[2 * i]; }
    else        { s = rs[i];     d = rd[i];     }
    int p = g_rowptr[d] + g_rank[i];
    g_csrs[p] = s;
    g_csra[p] = g_e[i];
}

// ---------------- SpMM 128-wide + ELU, fp32 out ------------------------------
__global__ void spmm128_elu_kernel(const float* __restrict__ hp,
                                   float* __restrict__ out, int N) {
    int gt = blockIdx.x * blockDim.x + threadIdx.x;
    int n = gt >> 5, lane = gt & 31;
    if (n >= N) return;
    int e  = g_rowptr[n];
    int e1 = g_rowptr[n + 1];
    float inv = (e1 > e) ? (1.f / g_esum[n]) : 0.f;
    float ax = 0.f, ay = 0.f, az = 0.f, aw = 0.f;
    const float4* hp4 = (const float4*)hp;
    for (; e + 4 <= e1; e += 4) {
        int   s0 = __ldg(&g_csrs[e]),     s1 = __ldg(&g_csrs[e + 1]);
        int   s2 = __ldg(&g_csrs[e + 2]), s3 = __ldg(&g_csrs[e + 3]);
        float a0 = __ldg(&g_csra[e]),     a1 = __ldg(&g_csra[e + 1]);
        float a2 = __ldg(&g_csra[e + 2]), a3 = __ldg(&g_csra[e + 3]);
        float4 v0 = __ldg(hp4 + (size_t)s0 * 32 + lane);
        float4 v1 = __ldg(hp4 + (size_t)s1 * 32 + lane);
        float4 v2 = __ldg(hp4 + (size_t)s2 * 32 + lane);
        float4 v3 = __ldg(hp4 + (size_t)s3 * 32 + lane);
        ax += a0 * v0.x + a1 * v1.x + a2 * v2.x + a3 * v3.x;
        ay += a0 * v0.y + a1 * v1.y + a2 * v2.y + a3 * v3.y;
        az += a0 * v0.z + a1 * v1.z + a2 * v2.z + a3 * v3.z;
        aw += a0 * v0.w + a1 * v1.w + a2 * v2.w + a3 * v3.w;
    }
    for (; e < e1; e++) {
        int   sA = __ldg(&g_csrs[e]);
        float aA = __ldg(&g_csra[e]);
        float4 vA = __ldg(hp4 + (size_t)sA * 32 + lane);
        ax += aA * vA.x; ay += aA * vA.y; az += aA * vA.z; aw += aA * vA.w;
    }
    ax *= inv; ay *= inv; az *= inv; aw *= inv;
    float4 r;
    r.x = (ax > 0.f) ? ax : expm1f(ax);
    r.y = (ay > 0.f) ? ay : expm1f(ay);
    r.z = (az > 0.f) ? az : expm1f(az);
    r.w = (aw > 0.f) ? aw : expm1f(aw);
    ((float4*)out)[(size_t)n * 32 + lane] = r;
}

// ---------------- SpMM 128-wide, writes split bf16 (no bias/act) -------------
__global__ void spmm128_split_kernel(const float* __restrict__ hp, int N) {
    int gt = blockIdx.x * blockDim.x + threadIdx.x;
    int n = gt >> 5, lane = gt & 31;
    if (n >= N) return;
    int e  = g_rowptr[n];
    int e1 = g_rowptr[n + 1];
    float inv = (e1 > e) ? (1.f / g_esum[n]) : 0.f;
    float ax = 0.f, ay = 0.f, az = 0.f, aw = 0.f;
    const float4* hp4 = (const float4*)hp;
    for (; e + 4 <= e1; e += 4) {
        int   s0 = __ldg(&g_csrs[e]),     s1 = __ldg(&g_csrs[e + 1]);
        int   s2 = __ldg(&g_csrs[e + 2]), s3 = __ldg(&g_csrs[e + 3]);
        float a0 = __ldg(&g_csra[e]),     a1 = __ldg(&g_csra[e + 1]);
        float a2 = __ldg(&g_csra[e + 2]), a3 = __ldg(&g_csra[e + 3]);
        float4 v0 = __ldg(hp4 + (size_t)s0 * 32 + lane);
        float4 v1 = __ldg(hp4 + (size_t)s1 * 32 + lane);
        float4 v2 = __ldg(hp4 + (size_t)s2 * 32 + lane);
        float4 v3 = __ldg(hp4 + (size_t)s3 * 32 + lane);
        ax += a0 * v0.x + a1 * v1.x + a2 * v2.x + a3 * v3.x;
        ay += a0 * v0.y + a1 * v1.y + a2 * v2.y + a3 * v3.y;
        az += a0 * v0.z + a1 * v1.z + a2 * v2.z + a3 * v3.z;
        aw += a0 * v0.w + a1 * v1.w + a2 * v2.w + a3 * v3.w;
    }
    for (; e < e1; e++) {
        int   sA = __ldg(&g_csrs[e]);
        float aA = __ldg(&g_csra[e]);
        float4 vA = __ldg(hp4 + (size_t)sA * 32 + lane);
        ax += aA * vA.x; ay += aA * vA.y; az += aA * vA.z; aw += aA * vA.w;
    }
    ax *= inv; ay *= inv; az *= inv; aw *= inv;
    uint2 hi, lo;
    split2(ax, ay, hi.x, lo.x);
    split2(az, aw, hi.y, lo.y);
    ((uint2*)g_sh)[(size_t)n * 32 + lane] = hi;
    ((uint2*)g_sl)[(size_t)n * 32 + lane] = lo;
}

// ---------------- SpMM 64-wide, fp32 out, no bias (middle aggregation) -------
__global__ void spmm64_mid_kernel(const float* __restrict__ hp,
                                  float* __restrict__ out, int N) {
    int gt = blockIdx.x * blockDim.x + threadIdx.x;
    int n = gt >> 5, lane = gt & 31;
    if (n >= N) return;
    int e  = g_rowptr[n];
    int e1 = g_rowptr[n + 1];
    float inv = (e1 > e) ? (1.f / g_esum[n]) : 0.f;
    float ax = 0.f, ay = 0.f;
    const float2* hp2 = (const float2*)hp;
    for (; e + 4 <= e1; e += 4) {
        int   s0 = __ldg(&g_csrs[e]),     s1 = __ldg(&g_csrs[e + 1]);
        int   s2 = __ldg(&g_csrs[e + 2]), s3 = __ldg(&g_csrs[e + 3]);
        float a0 = __ldg(&g_csra[e]),     a1 = __ldg(&g_csra[e + 1]);
        float a2 = __ldg(&g_csra[e + 2]), a3 = __ldg(&g_csra[e + 3]);
        float2 v0 = __ldg(hp2 + (size_t)s0 * 32 + lane);
        float2 v1 = __ldg(hp2 + (size_t)s1 * 32 + lane);
        float2 v2 = __ldg(hp2 + (size_t)s2 * 32 + lane);
        float2 v3 = __ldg(hp2 + (size_t)s3 * 32 + lane);
        ax += a0 * v0.x + a1 * v1.x + a2 * v2.x + a3 * v3.x;
        ay += a0 * v0.y + a1 * v1.y + a2 * v2.y + a3 * v3.y;
    }
    for (; e < e1; e++) {
        int   sA = __ldg(&g_csrs[e]);
        float aA = __ldg(&g_csra[e]);
        float2 vA = __ldg(hp2 + (size_t)sA * 32 + lane);
        ax += aA * vA.x; ay += aA * vA.y;
    }
    ((float2*)out)[(size_t)n * 32 + lane] = make_float2(ax * inv, ay * inv);
}

// ---------------- SpMM 64-wide final: bias = bb if row has edges else bc -----
__global__ void spmm64_final_kernel(const float* __restrict__ hp,
                                    const float* __restrict__ bc,
                                    float* __restrict__ out, int N) {
    int gt = blockIdx.x * blockDim.x + threadIdx.x;
    int n = gt >> 5, lane = gt & 31;
    if (n >= N) return;
    int e  = g_rowptr[n];
    int e1 = g_rowptr[n + 1];
    bool has = (e1 > e);
    float inv = has ? (1.f / g_esum[n]) : 0.f;
    float ax = 0.f, ay = 0.f;
    const float2* hp2 = (const float2*)hp;
    for (; e + 4 <= e1; e += 4) {
        int   s0 = __ldg(&g_csrs[e]),     s1 = __ldg(&g_csrs[e + 1]);
        int   s2 = __ldg(&g_csrs[e + 2]), s3 = __ldg(&g_csrs[e + 3]);
        float a0 = __ldg(&g_csra[e]),     a1 = __ldg(&g_csra[e + 1]);
        float a2 = __ldg(&g_csra[e + 2]), a3 = __ldg(&g_csra[e + 3]);
        float2 v0 = __ldg(hp2 + (size_t)s0 * 32 + lane);
        float2 v1 = __ldg(hp2 + (size_t)s1 * 32 + lane);
        float2 v2 = __ldg(hp2 + (size_t)s2 * 32 + lane);
        float2 v3 = __ldg(hp2 + (size_t)s3 * 32 + lane);
        ax += a0 * v0.x + a1 * v1.x + a2 * v2.x + a3 * v3.x;
        ay += a0 * v0.y + a1 * v1.y + a2 * v2.y + a3 * v3.y;
    }
    for (; e < e1; e++) {
        int   sA = __ldg(&g_csrs[e]);
        float aA = __ldg(&g_csra[e]);
        float2 vA = __ldg(hp2 + (size_t)sA * 32 + lane);
        ax += aA * vA.x; ay += aA * vA.y;
    }
    float2 bv;
    if (has) bv = *(const float2*)&g_bb[lane * 2];          // b2@Wc + bc
    else     bv = __ldg((const float2*)bc + lane);          // isolated: bc
    ((float2*)out)[(size_t)n * 32 + lane] =
        make_float2(ax * inv + bv.x, ay * inv + bv.y);
}

// ---------------- launch -----------------------------------------------------
extern "C" void kernel_launch(void* const* d_in, const int* in_sizes, int n_in,
                              void* d_out, int out_size) {
    const float* x    = (const float*)d_in[0];
    const int*   srcR = (const int*)d_in[1];
    const int*   dstR = (const int*)d_in[2];
    const float* Wg   = (const float*)d_in[3];
    const float* al   = (const float*)d_in[4];
    const float* ar   = (const float*)d_in[5];
    const float* W1   = (const float*)d_in[6];
    const float* b1   = (const float*)d_in[7];
    const float* W2   = (const float*)d_in[8];
    const float* b2   = (const float*)d_in[9];
    const float* Wc   = (const float*)d_in[10];
    const float* bc   = (const float*)d_in[11];
    float* out = (float*)d_out;

    const int N = in_sizes[0] / HD;
    const int E = in_sizes[1];

    float *dh, *dt2, *db1M;
    __nv_bfloat16 *dsh, *dsl, *dwh, *dwl;
    cudaGetSymbolAddress((void**)&dh,   g_h);
    cudaGetSymbolAddress((void**)&dt2,  g_t2);
    cudaGetSymbolAddress((void**)&db1M, g_b1M);
    cudaGetSymbolAddress((void**)&dsh,  g_sh);
    cudaGetSymbolAddress((void**)&dsl,  g_sl);
    cudaGetSymbolAddress((void**)&dwh,  g_whT);
    cudaGetSymbolAddress((void**)&dwl,  g_wlT);

    const int smem128 = 64 * 256 * 2 + 128 * 256 * 2;  // 98304 B
    const int smem64  = 64 * 256 * 2 + 64 * 256 * 2;   // 65536 B
    cudaFuncSetAttribute(gemm_mma_kernel<128>,
                         cudaFuncAttributeMaxDynamicSharedMemorySize, smem128);
    cudaFuncSetAttribute(gemm_mma_kernel<64>,
                         cudaFuncAttributeMaxDynamicSharedMemorySize, smem64);

    const int eb  = (E + 255) / 256;
    const int sb  = (N + 255) / 256;        // scan/init blocks
    const int nwb = (N * 32 + 255) / 256;   // warp-per-node kernels
    const int gb  = (N + 63) / 64;          // gemm blocks
    const int nxb = (N * 32 + 255) / 256;   // xsplit blocks

    // prelude1: Wg split (64) + M (32) + bb (1) + wl/wr (1) + detect (1) + init (sb)
    prelude1_kernel<<<64 + 32 + 1 + 1 + 1 + sb, 256>>>(
        Wg, W2, Wc, b2, bc, al, ar, srcR, N, E);
    // prelude2: W1M split (32) + b1M (1) + xsplit-with-el/er (nxb)
    prelude2_kernel<<<32 + 1 + nxb, 256>>>(W1, b1, x, N);

    // edge pass (needs only el/er from prelude2) -> CSR
    edge_pass_kernel<<<eb, 256>>>(srcR, dstR, E);
    scan1_kernel<<<sb, 256>>>(N);
    scan3_kernel<<<sb, 256>>>(N, E, sb);
    scatter_kernel<<<eb, 256>>>(srcR, dstR, E);

    // GAT projection: h = x @ W_gat (needed only by the first aggregation)
    gemm_mma_kernel<128><<<gb, 256, smem128>>>(dsh, dsl, dwh, dwl, nullptr, dh, N);

    // h1 = elu(P@h)                  (fp32)
    spmm128_elu_kernel<<<nwb, 256>>>(dh, dt2, N);
    // g  = P@h1                      (split bf16)
    spmm128_split_kernel<<<nwb, 256>>>(dt2, N);
    // v  = g @ W1M + b1M             (== h2 @ M, exact identity)
    gemm_mma_kernel<64><<<gb, 256, smem64>>>(dsh, dsl, dwh + 16384, dwl + 16384, db1M, dt2, N);
    // u  = P@v
    spmm64_mid_kernel<<<nwb, 256>>>(dt2, dh, N);
    // logits = P@u + (bb | bc)
    spmm64_final_kernel<<<nwb, 256>>>(dh, bc, out, N);
}